// round 10
// baseline (speedup 1.0000x reference)
#include <cuda_runtime.h>
#include <cuda_bf16.h>
#include <math.h>

#define BB 2
#define TT 2048
#define CC 2048
#define HH 16
#define DD 128
#define C3 (3*CC)
#define BT (BB*TT)

// ---------------- device scratch (static: no allocations allowed) ----------------
__device__ float g_qkv[(size_t)BT * C3];            // [B,T,3C] fp32 (tf32-rounded values)
__device__ unsigned g_xh[(size_t)BT * CC / 2];      // x hi  (bf16 pairs, [M][K/2] words)
__device__ unsigned g_xl[(size_t)BT * CC / 2];      // x lo
__device__ unsigned g_ah[(size_t)BT * CC / 2];      // attn out hi
__device__ unsigned g_al[(size_t)BT * CC / 2];      // attn out lo
__device__ unsigned g_wqkvh[(size_t)(CC/2) * C3];   // Wqkv hi, k-pair packed [K/2][N]
__device__ unsigned g_wqkvl[(size_t)(CC/2) * C3];
__device__ unsigned g_wouth[(size_t)(CC/2) * CC];
__device__ unsigned g_woutl[(size_t)(CC/2) * CC];
__device__ float g_cos[TT * 64];
__device__ float g_sin[TT * 64];
__device__ int   g_len[BB];

// ---------------- lengths from padding mask (dtype auto-detect) ----------------
__global__ void lengths_kernel(const void* mask) {
    __shared__ int ssum[256];
    int b = blockIdx.x;
    unsigned int w0 = *(const unsigned int*)mask;
    int cnt = 0;
    if (w0 == 0x01010101u) {
        const unsigned char* m = (const unsigned char*)mask + (size_t)b * TT;
        for (int i = threadIdx.x; i < TT; i += 256) cnt += (m[i] != 0);
    } else if (w0 == 0x3F800000u) {
        const float* m = (const float*)mask + (size_t)b * TT;
        for (int i = threadIdx.x; i < TT; i += 256) cnt += (m[i] != 0.0f);
    } else {
        const int* m = (const int*)mask + (size_t)b * TT;
        for (int i = threadIdx.x; i < TT; i += 256) cnt += (m[i] != 0);
    }
    ssum[threadIdx.x] = cnt;
    __syncthreads();
    for (int s = 128; s > 0; s >>= 1) {
        if (threadIdx.x < s) ssum[threadIdx.x] += ssum[threadIdx.x + s];
        __syncthreads();
    }
    if (threadIdx.x == 0) g_len[b] = ssum[0];
}

// ---------------- RoPE tables ----------------
__global__ void rope_table_kernel() {
    int idx = blockIdx.x * blockDim.x + threadIdx.x;
    if (idx >= TT * 64) return;
    int t = idx >> 6, i = idx & 63;
    float invf = (float)(1.0 / pow(10000.0, (double)i / 64.0));
    float ang = (float)t * invf;
    double a = (double)ang;
    g_cos[idx] = (float)cos(a);
    g_sin[idx] = (float)sin(a);
}

// ---------------- helpers ----------------
__device__ __forceinline__ unsigned smem_u32(const void* p) {
    return (unsigned)__cvta_generic_to_shared(p);
}
__device__ __forceinline__ float to_tf32(float x) {
    unsigned u;
    asm("cvt.rna.tf32.f32 %0, %1;" : "=r"(u) : "f"(x));
    return __uint_as_float(u);
}
__device__ __forceinline__ void mma_tf32(float* d, const unsigned* a, const unsigned* b) {
    asm volatile(
        "mma.sync.aligned.m16n8k8.row.col.f32.tf32.tf32.f32 "
        "{%0,%1,%2,%3}, {%4,%5,%6,%7}, {%8,%9}, {%0,%1,%2,%3};"
        : "+f"(d[0]), "+f"(d[1]), "+f"(d[2]), "+f"(d[3])
        : "r"(a[0]), "r"(a[1]), "r"(a[2]), "r"(a[3]), "r"(b[0]), "r"(b[1]));
}
__device__ __forceinline__ void mma_bf16(float* d, const unsigned* a, const unsigned* b) {
    asm volatile(
        "mma.sync.aligned.m16n8k16.row.col.f32.bf16.bf16.f32 "
        "{%0,%1,%2,%3}, {%4,%5,%6,%7}, {%8,%9}, {%0,%1,%2,%3};"
        : "+f"(d[0]), "+f"(d[1]), "+f"(d[2]), "+f"(d[3])
        : "r"(a[0]), "r"(a[1]), "r"(a[2]), "r"(a[3]), "r"(b[0]), "r"(b[1]));
}
__device__ __forceinline__ unsigned pack_hi(float v0, float v1, float &r0, float &r1) {
    __nv_bfloat16 h0 = __float2bfloat16(v0);
    __nv_bfloat16 h1 = __float2bfloat16(v1);
    r0 = v0 - __bfloat162float(h0);
    r1 = v1 - __bfloat162float(h1);
    unsigned u0 = __bfloat16_as_ushort(h0), u1 = __bfloat16_as_ushort(h1);
    return u0 | (u1 << 16);
}
__device__ __forceinline__ unsigned pack_bf(float v0, float v1) {
    unsigned u0 = __bfloat16_as_ushort(__float2bfloat16(v0));
    unsigned u1 = __bfloat16_as_ushort(__float2bfloat16(v1));
    return u0 | (u1 << 16);
}

// ---------------- in-place RoPE on Q and K slices of g_qkv (tf32-rounded out) -----
__global__ void rope_apply_kernel() {
    int idx = blockIdx.x * blockDim.x + threadIdx.x;
    int i = idx & 63; int r = idx >> 6;
    int h = r & (HH - 1); r >>= 4;
    int w = r & 1; r >>= 1;
    int t = r & (TT - 1); r >>= 11;
    int b = r;
    size_t base = ((size_t)(b * TT + t)) * C3 + (size_t)w * CC + (size_t)h * DD;
    float c = g_cos[t * 64 + i], s = g_sin[t * 64 + i];
    float x1 = g_qkv[base + i], x2 = g_qkv[base + 64 + i];
    float y1 = x1 * c - x2 * s;
    float y2 = x2 * c + x1 * s;
    if (w == 0) {                                   // Q: pre-scale by 1/sqrt(d)
        const float scale = 0.08838834764831845f;
        y1 *= scale; y2 *= scale;
    }
    g_qkv[base + i]      = to_tf32(y1);
    g_qkv[base + 64 + i] = to_tf32(y2);
}

// ---------------- split kernels ----------------
__global__ void split_a_kernel(const float* __restrict__ src, unsigned* __restrict__ dh,
                               unsigned* __restrict__ dl, size_t nwords) {
    size_t w = (size_t)blockIdx.x * blockDim.x + threadIdx.x;
    if (w >= nwords) return;
    float2 v = *(const float2*)&src[w * 2];
    float l0, l1;
    dh[w] = pack_hi(v.x, v.y, l0, l1);
    dl[w] = pack_bf(l0, l1);
}

__global__ void split_b_kernel(const float* __restrict__ W, unsigned* __restrict__ dh,
                               unsigned* __restrict__ dl, int K, int N) {
    size_t idx = (size_t)blockIdx.x * blockDim.x + threadIdx.x;
    size_t tot = (size_t)(K / 2) * N;
    if (idx >= tot) return;
    int n = (int)(idx % N);
    int k2 = (int)(idx / N);
    float v0 = W[(size_t)(2 * k2) * N + n];
    float v1 = W[(size_t)(2 * k2 + 1) * N + n];
    float l0, l1;
    dh[idx] = pack_hi(v0, v1, l0, l1);
    dl[idx] = pack_bf(l0, l1);
}

// ================= bf16x3 tensor-core GEMM: C[M,N] = A[M,K] @ B[K,N] ==============
#define KCB 32
#define ASTRW 20
#define BSTRW 136
#define ATILEW (128 * ASTRW)
#define BTILEW (16 * BSTRW)
#define GEMM_SMEM ((4 * ATILEW + 4 * BTILEW) * 4)

__device__ __forceinline__ void gemm_load_chunk_bf(
    unsigned* Ah, unsigned* Al, unsigned* Bh, unsigned* Bl,
    const unsigned* __restrict__ Agh, const unsigned* __restrict__ Agl,
    const unsigned* __restrict__ Bgh, const unsigned* __restrict__ Bgl,
    int row0, int col0, int kc, int K, int N, int tid)
{
    const int Kw = K >> 1;
#pragma unroll
    for (int i = 0; i < 4; i++) {
        int c = i * 128 + tid;
        int row = c >> 2, segw = (c & 3) << 2;
        size_t gsrc = (size_t)(row0 + row) * Kw + (kc >> 1) + segw;
        int dstw = row * ASTRW + segw;
        asm volatile("cp.async.cg.shared.global [%0], [%1], 16;"
                     :: "r"(smem_u32(Ah + dstw)), "l"(Agh + gsrc));
        asm volatile("cp.async.cg.shared.global [%0], [%1], 16;"
                     :: "r"(smem_u32(Al + dstw)), "l"(Agl + gsrc));
    }
#pragma unroll
    for (int i = 0; i < 4; i++) {
        int c = i * 128 + tid;
        int krow = c >> 5, segw = (c & 31) << 2;
        size_t gsrc = (size_t)((kc >> 1) + krow) * N + col0 + segw;
        int dstw = krow * BSTRW + segw;
        asm volatile("cp.async.cg.shared.global [%0], [%1], 16;"
                     :: "r"(smem_u32(Bh + dstw)), "l"(Bgh + gsrc));
        asm volatile("cp.async.cg.shared.global [%0], [%1], 16;"
                     :: "r"(smem_u32(Bl + dstw)), "l"(Bgl + gsrc));
    }
    asm volatile("cp.async.commit_group;");
}

__global__ __launch_bounds__(128, 2) void gemm_bf16x3_kernel(
    const unsigned* __restrict__ Agh, const unsigned* __restrict__ Agl,
    const unsigned* __restrict__ Bgh, const unsigned* __restrict__ Bgl,
    float* __restrict__ C, int M, int N, int K, int round_out)
{
    extern __shared__ unsigned smw[];
    unsigned* Ah = smw;
    unsigned* Al = smw + 2 * ATILEW;
    unsigned* Bh = smw + 4 * ATILEW;
    unsigned* Bl = smw + 4 * ATILEW + 2 * BTILEW;

    const int tid  = threadIdx.x;
    const int lane = tid & 31, warp = tid >> 5;
    const int wr = warp >> 1, wc = warp & 1;
    const int gr = lane >> 2, tig = lane & 3;
    const int row0 = blockIdx.y * 128, col0 = blockIdx.x * 128;

    float acc[4][8][4];
#pragma unroll
    for (int mi = 0; mi < 4; mi++)
#pragma unroll
        for (int ni = 0; ni < 8; ni++)
#pragma unroll
            for (int r = 0; r < 4; r++) acc[mi][ni][r] = 0.f;

    const int nc = K / KCB;
    gemm_load_chunk_bf(Ah, Al, Bh, Bl, Agh, Agl, Bgh, Bgl, row0, col0, 0, K, N, tid);

    for (int c = 0; c < nc; c++) {
        if (c + 1 < nc) {
            int nb = (c + 1) & 1;
            gemm_load_chunk_bf(Ah + nb * ATILEW, Al + nb * ATILEW,
                               Bh + nb * BTILEW, Bl + nb * BTILEW,
                               Agh, Agl, Bgh, Bgl, row0, col0, (c + 1) * KCB, K, N, tid);
            asm volatile("cp.async.wait_group 1;");
        } else {
            asm volatile("cp.async.wait_group 0;");
        }
        __syncthreads();

        const unsigned* ah = Ah + (c & 1) * ATILEW;
        const unsigned* al = Al + (c & 1) * ATILEW;
        const unsigned* bh = Bh + (c & 1) * BTILEW;
        const unsigned* bl = Bl + (c & 1) * BTILEW;

#pragma unroll
        for (int s = 0; s < 2; s++) {
            const int kw = s * 8;
            unsigned afh[4][4], afl[4][4], bfh[8][2], bfl[8][2];
#pragma unroll
            for (int mi = 0; mi < 4; mi++) {
                int m0 = wr * 64 + mi * 16;
                int w0 = (m0 + gr) * ASTRW + kw + tig;
                int w1 = (m0 + 8 + gr) * ASTRW + kw + tig;
                afh[mi][0] = ah[w0];     afh[mi][1] = ah[w1];
                afh[mi][2] = ah[w0 + 4]; afh[mi][3] = ah[w1 + 4];
                afl[mi][0] = al[w0];     afl[mi][1] = al[w1];
                afl[mi][2] = al[w0 + 4]; afl[mi][3] = al[w1 + 4];
            }
#pragma unroll
            for (int ni = 0; ni < 8; ni++) {
                int n0 = wc * 64 + ni * 8;
                int w0 = (kw + tig) * BSTRW + n0 + gr;
                int w1 = (kw + 4 + tig) * BSTRW + n0 + gr;
                bfh[ni][0] = bh[w0]; bfh[ni][1] = bh[w1];
                bfl[ni][0] = bl[w0]; bfl[ni][1] = bl[w1];
            }
#pragma unroll
            for (int mi = 0; mi < 4; mi++)
#pragma unroll
                for (int ni = 0; ni < 8; ni++) {
                    mma_bf16(acc[mi][ni], afl[mi], bfh[ni]);
                    mma_bf16(acc[mi][ni], afh[mi], bfl[ni]);
                    mma_bf16(acc[mi][ni], afh[mi], bfh[ni]);
                }
        }
        __syncthreads();
    }

#pragma unroll
    for (int mi = 0; mi < 4; mi++) {
        int m0 = row0 + wr * 64 + mi * 16;
#pragma unroll
        for (int ni = 0; ni < 8; ni++) {
            int n0 = col0 + wc * 64 + ni * 8 + 2 * tig;
            float v0 = acc[mi][ni][0], v1 = acc[mi][ni][1];
            float v2 = acc[mi][ni][2], v3 = acc[mi][ni][3];
            if (round_out) {
                v0 = to_tf32(v0); v1 = to_tf32(v1);
                v2 = to_tf32(v2); v3 = to_tf32(v3);
            }
            float* p0 = C + (size_t)(m0 + gr) * N + n0;
            float* p1 = C + (size_t)(m0 + 8 + gr) * N + n0;
            p0[0] = v0; p0[1] = v1;
            p1[0] = v2; p1[1] = v3;
        }
    }
}

// ========== tf32 flash attention, causal, 64x64 tiles, D=128, cp.async K/V ========
// qkv already tf32-rounded (GEMM1 + rope); Q pre-scaled. K/V double-buffered.
#define QSTR 132
#define VSTR 136
#define SSTR 68
#define SM_Q 0
#define SM_K (SM_Q + 64 * QSTR)            // 2 buffers of 64*QSTR
#define SM_V (SM_K + 2 * 64 * QSTR)        // 2 buffers of 64*VSTR
#define SM_S (SM_V + 2 * 64 * VSTR)
#define SM_ST (SM_S + 64 * SSTR)
#define ATT_SMEM_BYTES ((SM_ST + 192) * 4)

__device__ __forceinline__ void load_kv_async(
    const float* __restrict__ Kg, const float* __restrict__ Vg,
    float* Ks, float* Vs, int kt, int tid)
{
#pragma unroll
    for (int l = 0; l < 8; l++) {
        int lin = l * 256 + tid;
        int row = lin >> 5, c4 = (lin & 31) << 2;
        size_t gofs = (size_t)(kt * 64 + row) * C3 + c4;
        asm volatile("cp.async.cg.shared.global [%0], [%1], 16;"
                     :: "r"(smem_u32(Ks + row * QSTR + c4)), "l"(Kg + gofs));
        asm volatile("cp.async.cg.shared.global [%0], [%1], 16;"
                     :: "r"(smem_u32(Vs + row * VSTR + c4)), "l"(Vg + gofs));
    }
    asm volatile("cp.async.commit_group;" ::: "memory");
}

__global__ __launch_bounds__(256, 1) void attn_kernel() {
    extern __shared__ float sm[];
    float* Qs = sm + SM_Q;
    float* Ksb[2] = { sm + SM_K, sm + SM_K + 64 * QSTR };
    float* Vsb[2] = { sm + SM_V, sm + SM_V + 64 * VSTR };
    float* Ss = sm + SM_S;
    float* mrow = sm + SM_ST;
    float* lrow = mrow + 64;
    float* crow = lrow + 64;

    const int tid = threadIdx.x;
    const int lane = tid & 31, warp = tid >> 5;
    const int gr = lane >> 2, tig = lane & 3;
    const int wr = warp >> 1, wn = warp & 1;
    const int m0 = wr * 16;
    const int bh = blockIdx.y;
    const int b = bh >> 4, h = bh & 15;
    const int qi = (int)gridDim.x - 1 - (int)blockIdx.x;
    const int qbase = qi * 64;

    const float* Qg = g_qkv + (size_t)b * TT * C3 + (size_t)h * DD;
    const float* Kg = Qg + CC;
    const float* Vg = Qg + 2 * CC;

    // prefetch K/V tile 0
    load_kv_async(Kg, Vg, Ksb[0], Vsb[0], 0, tid);

    // load Q tile (already tf32-rounded + scaled)
#pragma unroll
    for (int l = 0; l < 8; l++) {
        int lin = l * 256 + tid;
        int row = lin >> 5, c4 = (lin & 31) << 2;
        *(float4*)&Qs[row * QSTR + c4] =
            *(const float4*)&Qg[(size_t)(qbase + row) * C3 + c4];
    }
    if (tid < 64) { mrow[tid] = -INFINITY; lrow[tid] = 0.f; }

    float oacc[8][4];
#pragma unroll
    for (int ni = 0; ni < 8; ni++)
#pragma unroll
        for (int r = 0; r < 4; r++) oacc[ni][r] = 0.f;

    for (int kt = 0; kt <= qi; kt++) {
        const int cur = kt & 1;
        if (kt < qi) {
            load_kv_async(Kg, Vg, Ksb[cur ^ 1], Vsb[cur ^ 1], kt + 1, tid);
            asm volatile("cp.async.wait_group 1;" ::: "memory");
        } else {
            asm volatile("cp.async.wait_group 0;" ::: "memory");
        }
        __syncthreads();

        const float* Ks = Ksb[cur];
        const float* Vs = Vsb[cur];

        float sa[4][4];
#pragma unroll
        for (int ni = 0; ni < 4; ni++)
#pragma unroll
            for (int r = 0; r < 4; r++) sa[ni][r] = 0.f;

#pragma unroll
        for (int ks = 0; ks < 16; ks++) {
            const int k0 = ks * 8;
            unsigned a[4];
            a[0] = __float_as_uint(Qs[(m0 + gr)     * QSTR + k0 + tig]);
            a[1] = __float_as_uint(Qs[(m0 + 8 + gr) * QSTR + k0 + tig]);
            a[2] = __float_as_uint(Qs[(m0 + gr)     * QSTR + k0 + 4 + tig]);
            a[3] = __float_as_uint(Qs[(m0 + 8 + gr) * QSTR + k0 + 4 + tig]);
#pragma unroll
            for (int ni = 0; ni < 4; ni++) {
                int n0 = wn * 32 + ni * 8;
                unsigned bfr[2];
                bfr[0] = __float_as_uint(Ks[(n0 + gr) * QSTR + k0 + tig]);
                bfr[1] = __float_as_uint(Ks[(n0 + gr) * QSTR + k0 + 4 + tig]);
                mma_tf32(sa[ni], a, bfr);
            }
        }

        const bool diag = (kt == qi);
#pragma unroll
        for (int ni = 0; ni < 4; ni++) {
            int c0 = wn * 32 + ni * 8 + 2 * tig;
            int r0 = m0 + gr, r1 = m0 + 8 + gr;
            float v0 = sa[ni][0], v1 = sa[ni][1];
            float v2 = sa[ni][2], v3 = sa[ni][3];
            if (diag) {
                if (c0     > r0) v0 = -INFINITY;
                if (c0 + 1 > r0) v1 = -INFINITY;
                if (c0     > r1) v2 = -INFINITY;
                if (c0 + 1 > r1) v3 = -INFINITY;
            }
            Ss[r0 * SSTR + c0] = v0; Ss[r0 * SSTR + c0 + 1] = v1;
            Ss[r1 * SSTR + c0] = v2; Ss[r1 * SSTR + c0 + 1] = v3;
        }
        __syncthreads();

        {
            int r = tid >> 2, sub = tid & 3;
            int cbase = sub * 16;
            float mx = -INFINITY;
#pragma unroll
            for (int c = 0; c < 16; c++) mx = fmaxf(mx, Ss[r * SSTR + cbase + c]);
            mx = fmaxf(mx, __shfl_xor_sync(0xffffffffu, mx, 1));
            mx = fmaxf(mx, __shfl_xor_sync(0xffffffffu, mx, 2));
            float mold = mrow[r];
            float mnew = fmaxf(mold, mx);
            float s = 0.f;
#pragma unroll
            for (int c = 0; c < 16; c++) {
                float sv = Ss[r * SSTR + cbase + c];
                float p = (sv == -INFINITY) ? 0.f : __expf(sv - mnew);
                Ss[r * SSTR + cbase + c] = to_tf32(p);
                s += p;
            }
            s += __shfl_xor_sync(0xffffffffu, s, 1);
            s += __shfl_xor_sync(0xffffffffu, s, 2);
            if (sub == 0) {
                float cf = (mold == -INFINITY) ? 0.f : __expf(mold - mnew);
                lrow[r] = lrow[r] * cf + s;
                mrow[r] = mnew;
                crow[r] = cf;
            }
        }
        __syncthreads();

        {
            float cf0 = crow[m0 + gr], cf1 = crow[m0 + 8 + gr];
#pragma unroll
            for (int ni = 0; ni < 8; ni++) {
                oacc[ni][0] *= cf0; oacc[ni][1] *= cf0;
                oacc[ni][2] *= cf1; oacc[ni][3] *= cf1;
            }
        }
#pragma unroll
        for (int ks = 0; ks < 8; ks++) {
            const int k0 = ks * 8;
            unsigned a[4];
            a[0] = __float_as_uint(Ss[(m0 + gr)     * SSTR + k0 + tig]);
            a[1] = __float_as_uint(Ss[(m0 + 8 + gr) * SSTR + k0 + tig]);
            a[2] = __float_as_uint(Ss[(m0 + gr)     * SSTR + k0 + 4 + tig]);
            a[3] = __float_as_uint(Ss[(m0 + 8 + gr) * SSTR + k0 + 4 + tig]);
#pragma unroll
            for (int ni = 0; ni < 8; ni++) {
                int n0 = wn * 64 + ni * 8;
                unsigned bfr[2];
                bfr[0] = __float_as_uint(Vs[(k0 + tig)     * VSTR + n0 + gr]);
                bfr[1] = __float_as_uint(Vs[(k0 + 4 + tig) * VSTR + n0 + gr]);
                mma_tf32(oacc[ni], a, bfr);
            }
        }
        __syncthreads();
    }

    // epilogue: normalize, zero padded rows, write bf16 hi/lo (A operand of out-GEMM)
    {
        int len = g_len[b];
        int r0 = m0 + gr, r1 = m0 + 8 + gr;
        int t0 = qbase + r0, t1 = qbase + r1;
        float inv0 = (t0 < len) ? 1.0f / lrow[r0] : 0.f;
        float inv1 = (t1 < len) ? 1.0f / lrow[r1] : 0.f;
        size_t base0 = (((size_t)b * TT + t0) * CC + (size_t)h * DD) >> 1;
        size_t base1 = (((size_t)b * TT + t1) * CC + (size_t)h * DD) >> 1;
#pragma unroll
        for (int ni = 0; ni < 8; ni++) {
            int c = wn * 64 + ni * 8 + 2 * tig;
            float o0 = oacc[ni][0] * inv0, o1 = oacc[ni][1] * inv0;
            float o2 = oacc[ni][2] * inv1, o3 = oacc[ni][3] * inv1;
            float l0, l1, l2, l3;
            g_ah[base0 + (c >> 1)] = pack_hi(o0, o1, l0, l1);
            g_al[base0 + (c >> 1)] = pack_bf(l0, l1);
            g_ah[base1 + (c >> 1)] = pack_hi(o2, o3, l2, l3);
            g_al[base1 + (c >> 1)] = pack_bf(l2, l3);
        }
    }
}

// ---------------- launch ----------------
extern "C" void kernel_launch(void* const* d_in, const int* in_sizes, int n_in,
                              void* d_out, int out_size) {
    const float* x    = (const float*)d_in[0];
    const void*  mask = d_in[1];
    const float* Wqkv = (const float*)d_in[2];
    const float* Wout = (const float*)d_in[3];
    float* out = (float*)d_out;

    float* qkv;    cudaGetSymbolAddress((void**)&qkv,    g_qkv);
    unsigned *xh, *xl, *ah, *al, *wqh, *wql, *woh, *wol;
    cudaGetSymbolAddress((void**)&xh,  g_xh);
    cudaGetSymbolAddress((void**)&xl,  g_xl);
    cudaGetSymbolAddress((void**)&ah,  g_ah);
    cudaGetSymbolAddress((void**)&al,  g_al);
    cudaGetSymbolAddress((void**)&wqh, g_wqkvh);
    cudaGetSymbolAddress((void**)&wql, g_wqkvl);
    cudaGetSymbolAddress((void**)&woh, g_wouth);
    cudaGetSymbolAddress((void**)&wol, g_woutl);

    lengths_kernel<<<BB, 256>>>(mask);
    rope_table_kernel<<<(TT * 64 + 255) / 256, 256>>>();

    // pre-split operands to bf16 hi/lo
    {
        size_t nw = (size_t)BT * CC / 2;
        split_a_kernel<<<(unsigned)((nw + 255) / 256), 256>>>(x, xh, xl, nw);
        size_t nq = (size_t)(CC / 2) * C3;
        split_b_kernel<<<(unsigned)((nq + 255) / 256), 256>>>(Wqkv, wqh, wql, CC, C3);
        size_t no = (size_t)(CC / 2) * CC;
        split_b_kernel<<<(unsigned)((no + 255) / 256), 256>>>(Wout, woh, wol, CC, CC);
    }

    cudaFuncSetAttribute(gemm_bf16x3_kernel, cudaFuncAttributeMaxDynamicSharedMemorySize, GEMM_SMEM);

    // qkv = x @ Wqkv  (bf16x3 tensor cores; outputs tf32-rounded for attention)
    gemm_bf16x3_kernel<<<dim3(C3 / 128, BT / 128), 128, GEMM_SMEM>>>(
        xh, xl, wqh, wql, qkv, BT, C3, CC, 1);

    // RoPE in place on Q,K (writes tf32-rounded; Q pre-scaled)
    rope_apply_kernel<<<(BB * TT * 2 * HH * 64) / 256, 256>>>();

    // causal flash attention (tf32 mma.sync, cp.async double-buffered K/V)
    cudaFuncSetAttribute(attn_kernel, cudaFuncAttributeMaxDynamicSharedMemorySize, ATT_SMEM_BYTES);
    attn_kernel<<<dim3(TT / 64, BB * HH), 256, ATT_SMEM_BYTES>>>();

    // out = attn @ Wout  (bf16x3 tensor cores; fp32 output)
    gemm_bf16x3_kernel<<<dim3(CC / 128, BT / 128), 128, GEMM_SMEM>>>(
        ah, al, woh, wol, out, BT, CC, CC, 0);
}

// round 11
// speedup vs baseline: 1.1541x; 1.1541x over previous
#include <cuda_runtime.h>
#include <cuda_bf16.h>
#include <cuda_fp16.h>
#include <math.h>

#define BB 2
#define TT 2048
#define CC 2048
#define HH 16
#define DD 128
#define C3 (3*CC)
#define BT (BB*TT)

// ---------------- device scratch ----------------
__device__ float g_qkv[(size_t)BT * C3];
__device__ unsigned g_xh[(size_t)BT * CC / 2];
__device__ unsigned g_xl[(size_t)BT * CC / 2];
__device__ unsigned g_ah[(size_t)BT * CC / 2];
__device__ unsigned g_al[(size_t)BT * CC / 2];
__device__ unsigned g_wqkvh[(size_t)(CC/2) * C3];
__device__ unsigned g_wqkvl[(size_t)(CC/2) * C3];
__device__ unsigned g_wouth[(size_t)(CC/2) * CC];
__device__ unsigned g_woutl[(size_t)(CC/2) * CC];
__device__ float g_cos[TT * 64];
__device__ float g_sin[TT * 64];
__device__ int   g_len[BB];

// ---------------- lengths ----------------
__global__ void lengths_kernel(const void* mask) {
    __shared__ int ssum[256];
    int b = blockIdx.x;
    unsigned int w0 = *(const unsigned int*)mask;
    int cnt = 0;
    if (w0 == 0x01010101u) {
        const unsigned char* m = (const unsigned char*)mask + (size_t)b * TT;
        for (int i = threadIdx.x; i < TT; i += 256) cnt += (m[i] != 0);
    } else if (w0 == 0x3F800000u) {
        const float* m = (const float*)mask + (size_t)b * TT;
        for (int i = threadIdx.x; i < TT; i += 256) cnt += (m[i] != 0.0f);
    } else {
        const int* m = (const int*)mask + (size_t)b * TT;
        for (int i = threadIdx.x; i < TT; i += 256) cnt += (m[i] != 0);
    }
    ssum[threadIdx.x] = cnt;
    __syncthreads();
    for (int s = 128; s > 0; s >>= 1) {
        if (threadIdx.x < s) ssum[threadIdx.x] += ssum[threadIdx.x + s];
        __syncthreads();
    }
    if (threadIdx.x == 0) g_len[b] = ssum[0];
}

// ---------------- RoPE tables ----------------
__global__ void rope_table_kernel() {
    int idx = blockIdx.x * blockDim.x + threadIdx.x;
    if (idx >= TT * 64) return;
    int t = idx >> 6, i = idx & 63;
    float invf = (float)(1.0 / pow(10000.0, (double)i / 64.0));
    float ang = (float)t * invf;
    double a = (double)ang;
    g_cos[idx] = (float)cos(a);
    g_sin[idx] = (float)sin(a);
}

// ---------------- helpers ----------------
__device__ __forceinline__ unsigned smem_u32(const void* p) {
    return (unsigned)__cvta_generic_to_shared(p);
}
__device__ __forceinline__ float to_tf32(float x) {
    unsigned u;
    asm("cvt.rna.tf32.f32 %0, %1;" : "=r"(u) : "f"(x));
    return __uint_as_float(u);
}
__device__ __forceinline__ void mma_tf32(float* d, const unsigned* a, const unsigned* b) {
    asm volatile(
        "mma.sync.aligned.m16n8k8.row.col.f32.tf32.tf32.f32 "
        "{%0,%1,%2,%3}, {%4,%5,%6,%7}, {%8,%9}, {%0,%1,%2,%3};"
        : "+f"(d[0]), "+f"(d[1]), "+f"(d[2]), "+f"(d[3])
        : "r"(a[0]), "r"(a[1]), "r"(a[2]), "r"(a[3]), "r"(b[0]), "r"(b[1]));
}
__device__ __forceinline__ void mma_bf16(float* d, const unsigned* a, const unsigned* b) {
    asm volatile(
        "mma.sync.aligned.m16n8k16.row.col.f32.bf16.bf16.f32 "
        "{%0,%1,%2,%3}, {%4,%5,%6,%7}, {%8,%9}, {%0,%1,%2,%3};"
        : "+f"(d[0]), "+f"(d[1]), "+f"(d[2]), "+f"(d[3])
        : "r"(a[0]), "r"(a[1]), "r"(a[2]), "r"(a[3]), "r"(b[0]), "r"(b[1]));
}
__device__ __forceinline__ void mma_f16(float* d, const unsigned* a, const unsigned* b) {
    asm volatile(
        "mma.sync.aligned.m16n8k16.row.col.f32.f16.f16.f32 "
        "{%0,%1,%2,%3}, {%4,%5,%6,%7}, {%8,%9}, {%0,%1,%2,%3};"
        : "+f"(d[0]), "+f"(d[1]), "+f"(d[2]), "+f"(d[3])
        : "r"(a[0]), "r"(a[1]), "r"(a[2]), "r"(a[3]), "r"(b[0]), "r"(b[1]));
}
__device__ __forceinline__ void ldsm_x4_trans(unsigned* d, unsigned addr) {
    asm volatile("ldmatrix.sync.aligned.m8n8.x4.trans.shared.b16 {%0,%1,%2,%3}, [%4];"
                 : "=r"(d[0]), "=r"(d[1]), "=r"(d[2]), "=r"(d[3]) : "r"(addr));
}
__device__ __forceinline__ unsigned pack_h2(float a, float b) {
    __half2 h = __floats2half2_rn(a, b);
    return *(unsigned*)&h;
}
__device__ __forceinline__ unsigned pack_hi(float v0, float v1, float &r0, float &r1) {
    __nv_bfloat16 h0 = __float2bfloat16(v0);
    __nv_bfloat16 h1 = __float2bfloat16(v1);
    r0 = v0 - __bfloat162float(h0);
    r1 = v1 - __bfloat162float(h1);
    unsigned u0 = __bfloat16_as_ushort(h0), u1 = __bfloat16_as_ushort(h1);
    return u0 | (u1 << 16);
}
__device__ __forceinline__ unsigned pack_bf(float v0, float v1) {
    unsigned u0 = __bfloat16_as_ushort(__float2bfloat16(v0));
    unsigned u1 = __bfloat16_as_ushort(__float2bfloat16(v1));
    return u0 | (u1 << 16);
}

// ---------------- RoPE apply (tf32-rounded out; Q pre-scaled) ----------------
__global__ void rope_apply_kernel() {
    int idx = blockIdx.x * blockDim.x + threadIdx.x;
    int i = idx & 63; int r = idx >> 6;
    int h = r & (HH - 1); r >>= 4;
    int w = r & 1; r >>= 1;
    int t = r & (TT - 1); r >>= 11;
    int b = r;
    size_t base = ((size_t)(b * TT + t)) * C3 + (size_t)w * CC + (size_t)h * DD;
    float c = g_cos[t * 64 + i], s = g_sin[t * 64 + i];
    float x1 = g_qkv[base + i], x2 = g_qkv[base + 64 + i];
    float y1 = x1 * c - x2 * s;
    float y2 = x2 * c + x1 * s;
    if (w == 0) {
        const float scale = 0.08838834764831845f;
        y1 *= scale; y2 *= scale;
    }
    g_qkv[base + i]      = to_tf32(y1);
    g_qkv[base + 64 + i] = to_tf32(y2);
}

// ---------------- split kernels ----------------
__global__ void split_a_kernel(const float* __restrict__ src, unsigned* __restrict__ dh,
                               unsigned* __restrict__ dl, size_t nwords) {
    size_t w = (size_t)blockIdx.x * blockDim.x + threadIdx.x;
    if (w >= nwords) return;
    float2 v = *(const float2*)&src[w * 2];
    float l0, l1;
    dh[w] = pack_hi(v.x, v.y, l0, l1);
    dl[w] = pack_bf(l0, l1);
}

__global__ void split_b_kernel(const float* __restrict__ W, unsigned* __restrict__ dh,
                               unsigned* __restrict__ dl, int K, int N) {
    size_t idx = (size_t)blockIdx.x * blockDim.x + threadIdx.x;
    size_t tot = (size_t)(K / 2) * N;
    if (idx >= tot) return;
    int n = (int)(idx % N);
    int k2 = (int)(idx / N);
    float v0 = W[(size_t)(2 * k2) * N + n];
    float v1 = W[(size_t)(2 * k2 + 1) * N + n];
    float l0, l1;
    dh[idx] = pack_hi(v0, v1, l0, l1);
    dl[idx] = pack_bf(l0, l1);
}

// ================= bf16x3 tensor-core GEMM (R6-proven config) ==============
#define KCB 32
#define ASTRW 20
#define BSTRW 136
#define ATILEW (128 * ASTRW)
#define BTILEW (16 * BSTRW)
#define GEMM_SMEM ((4 * ATILEW + 4 * BTILEW) * 4)

__device__ __forceinline__ void gemm_load_chunk_bf(
    unsigned* Ah, unsigned* Al, unsigned* Bh, unsigned* Bl,
    const unsigned* __restrict__ Agh, const unsigned* __restrict__ Agl,
    const unsigned* __restrict__ Bgh, const unsigned* __restrict__ Bgl,
    int row0, int col0, int kc, int K, int N, int tid)
{
    const int Kw = K >> 1;
#pragma unroll
    for (int i = 0; i < 4; i++) {
        int c = i * 128 + tid;
        int row = c >> 2, segw = (c & 3) << 2;
        size_t gsrc = (size_t)(row0 + row) * Kw + (kc >> 1) + segw;
        int dstw = row * ASTRW + segw;
        asm volatile("cp.async.cg.shared.global [%0], [%1], 16;"
                     :: "r"(smem_u32(Ah + dstw)), "l"(Agh + gsrc));
        asm volatile("cp.async.cg.shared.global [%0], [%1], 16;"
                     :: "r"(smem_u32(Al + dstw)), "l"(Agl + gsrc));
    }
#pragma unroll
    for (int i = 0; i < 4; i++) {
        int c = i * 128 + tid;
        int krow = c >> 5, segw = (c & 31) << 2;
        size_t gsrc = (size_t)((kc >> 1) + krow) * N + col0 + segw;
        int dstw = krow * BSTRW + segw;
        asm volatile("cp.async.cg.shared.global [%0], [%1], 16;"
                     :: "r"(smem_u32(Bh + dstw)), "l"(Bgh + gsrc));
        asm volatile("cp.async.cg.shared.global [%0], [%1], 16;"
                     :: "r"(smem_u32(Bl + dstw)), "l"(Bgl + gsrc));
    }
    asm volatile("cp.async.commit_group;");
}

__global__ __launch_bounds__(128, 2) void gemm_bf16x3_kernel(
    const unsigned* __restrict__ Agh, const unsigned* __restrict__ Agl,
    const unsigned* __restrict__ Bgh, const unsigned* __restrict__ Bgl,
    float* __restrict__ C, int M, int N, int K, int round_out)
{
    extern __shared__ unsigned smw[];
    unsigned* Ah = smw;
    unsigned* Al = smw + 2 * ATILEW;
    unsigned* Bh = smw + 4 * ATILEW;
    unsigned* Bl = smw + 4 * ATILEW + 2 * BTILEW;

    const int tid  = threadIdx.x;
    const int lane = tid & 31, warp = tid >> 5;
    const int wr = warp >> 1, wc = warp & 1;
    const int gr = lane >> 2, tig = lane & 3;
    const int row0 = blockIdx.y * 128, col0 = blockIdx.x * 128;

    float acc[4][8][4];
#pragma unroll
    for (int mi = 0; mi < 4; mi++)
#pragma unroll
        for (int ni = 0; ni < 8; ni++)
#pragma unroll
            for (int r = 0; r < 4; r++) acc[mi][ni][r] = 0.f;

    const int nc = K / KCB;
    gemm_load_chunk_bf(Ah, Al, Bh, Bl, Agh, Agl, Bgh, Bgl, row0, col0, 0, K, N, tid);

    for (int c = 0; c < nc; c++) {
        if (c + 1 < nc) {
            int nb = (c + 1) & 1;
            gemm_load_chunk_bf(Ah + nb * ATILEW, Al + nb * ATILEW,
                               Bh + nb * BTILEW, Bl + nb * BTILEW,
                               Agh, Agl, Bgh, Bgl, row0, col0, (c + 1) * KCB, K, N, tid);
            asm volatile("cp.async.wait_group 1;");
        } else {
            asm volatile("cp.async.wait_group 0;");
        }
        __syncthreads();

        const unsigned* ah = Ah + (c & 1) * ATILEW;
        const unsigned* al = Al + (c & 1) * ATILEW;
        const unsigned* bh = Bh + (c & 1) * BTILEW;
        const unsigned* bl = Bl + (c & 1) * BTILEW;

#pragma unroll
        for (int s = 0; s < 2; s++) {
            const int kw = s * 8;
            unsigned afh[4][4], afl[4][4], bfh[8][2], bfl[8][2];
#pragma unroll
            for (int mi = 0; mi < 4; mi++) {
                int m0 = wr * 64 + mi * 16;
                int w0 = (m0 + gr) * ASTRW + kw + tig;
                int w1 = (m0 + 8 + gr) * ASTRW + kw + tig;
                afh[mi][0] = ah[w0];     afh[mi][1] = ah[w1];
                afh[mi][2] = ah[w0 + 4]; afh[mi][3] = ah[w1 + 4];
                afl[mi][0] = al[w0];     afl[mi][1] = al[w1];
                afl[mi][2] = al[w0 + 4]; afl[mi][3] = al[w1 + 4];
            }
#pragma unroll
            for (int ni = 0; ni < 8; ni++) {
                int n0 = wc * 64 + ni * 8;
                int w0 = (kw + tig) * BSTRW + n0 + gr;
                int w1 = (kw + 4 + tig) * BSTRW + n0 + gr;
                bfh[ni][0] = bh[w0]; bfh[ni][1] = bh[w1];
                bfl[ni][0] = bl[w0]; bfl[ni][1] = bl[w1];
            }
#pragma unroll
            for (int mi = 0; mi < 4; mi++)
#pragma unroll
                for (int ni = 0; ni < 8; ni++) {
                    mma_bf16(acc[mi][ni], afl[mi], bfh[ni]);
                    mma_bf16(acc[mi][ni], afh[mi], bfl[ni]);
                    mma_bf16(acc[mi][ni], afh[mi], bfh[ni]);
                }
        }
        __syncthreads();
    }

#pragma unroll
    for (int mi = 0; mi < 4; mi++) {
        int m0 = row0 + wr * 64 + mi * 16;
#pragma unroll
        for (int ni = 0; ni < 8; ni++) {
            int n0 = col0 + wc * 64 + ni * 8 + 2 * tig;
            float v0 = acc[mi][ni][0], v1 = acc[mi][ni][1];
            float v2 = acc[mi][ni][2], v3 = acc[mi][ni][3];
            if (round_out) {
                v0 = to_tf32(v0); v1 = to_tf32(v1);
                v2 = to_tf32(v2); v3 = to_tf32(v3);
            }
            float* p0 = C + (size_t)(m0 + gr) * N + n0;
            float* p1 = C + (size_t)(m0 + 8 + gr) * N + n0;
            p0[0] = v0; p0[1] = v1;
            p1[0] = v2; p1[1] = v3;
        }
    }
}

// ====== FA-2 style attention: BLK_M=128, 8 warps x (m16 x full n64), causal ======
// Warp-local softmax in registers; P kept as fp16 A-frags; V fp16 via ldmatrix.trans.
#define AQSTR 132                       // Q/K f32 row stride (words)
#define AVSH 136                        // V row stride in halves (272B)
#define SMW_Q 0                         // [128][AQSTR] f32
#define SMW_K (128 * AQSTR)             // [64][AQSTR] f32
#define SMW_V (SMW_K + 64 * AQSTR)      // fp16 [64][AVSH] = 64*68 words
#define ATT_SMEM_W (SMW_V + 64 * 68)
#define ATT_SMEM_BYTES (ATT_SMEM_W * 4)

__global__ __launch_bounds__(256, 1) void attn_kernel() {
    extern __shared__ float sm[];
    float* Qs = sm + SMW_Q;
    float* Ks = sm + SMW_K;
    unsigned* Vw = (unsigned*)(sm + SMW_V);
    const unsigned vbase = smem_u32(sm + SMW_V);

    const int tid = threadIdx.x;
    const int lane = tid & 31, wid = tid >> 5;
    const int gr = lane >> 2, tig = lane & 3;
    const int m0 = wid * 16;
    const int bh = blockIdx.y;
    const int b = bh >> 4, h = bh & 15;
    const int qi = (int)gridDim.x - 1 - (int)blockIdx.x;   // heavy tiles first
    const int qbase = qi * 128;

    const float* Qg = g_qkv + (size_t)b * TT * C3 + (size_t)h * DD;
    const float* Kg = Qg + CC;
    const float* Vg = Qg + 2 * CC;

    // warp-local Q load: warp wid owns rows m0..m0+15 (no barrier needed)
#pragma unroll
    for (int l = 0; l < 16; l++) {
        int row = m0 + l;
        int c4 = lane * 4;
        *(float4*)&Qs[row * AQSTR + c4] =
            *(const float4*)&Qg[(size_t)(qbase + row) * C3 + c4];
    }

    float mo0 = -INFINITY, mo1 = -INFINITY, lr0 = 0.f, lr1 = 0.f;
    float oacc[16][4];
#pragma unroll
    for (int ni = 0; ni < 16; ni++)
#pragma unroll
        for (int r = 0; r < 4; r++) oacc[ni][r] = 0.f;

    const int nkt = 2 * qi + 2;
    for (int kt = 0; kt < nkt; kt++) {
        __syncthreads();   // previous iteration's K/V reads complete
        // load K (f32) and V (fp16-converted), 64x128 each
#pragma unroll
        for (int l = 0; l < 8; l++) {
            int lin = l * 256 + tid;
            int row = lin >> 5, c4 = (lin & 31) << 2;
            size_t gofs = (size_t)(kt * 64 + row) * C3 + c4;
            *(float4*)&Ks[row * AQSTR + c4] = *(const float4*)&Kg[gofs];
            float4 vv = *(const float4*)&Vg[gofs];
            unsigned h01 = pack_h2(vv.x, vv.y);
            unsigned h23 = pack_h2(vv.z, vv.w);
            *(uint2*)&Vw[row * 68 + (c4 >> 1)] = make_uint2(h01, h23);
        }
        __syncthreads();

        // S = Q K^T : m16 x n64, tf32
        float sa[8][4];
#pragma unroll
        for (int ni = 0; ni < 8; ni++)
#pragma unroll
            for (int r = 0; r < 4; r++) sa[ni][r] = 0.f;

#pragma unroll
        for (int ks = 0; ks < 16; ks++) {
            const int k0 = ks * 8;
            unsigned a[4];
            a[0] = __float_as_uint(Qs[(m0 + gr)     * AQSTR + k0 + tig]);
            a[1] = __float_as_uint(Qs[(m0 + 8 + gr) * AQSTR + k0 + tig]);
            a[2] = __float_as_uint(Qs[(m0 + gr)     * AQSTR + k0 + 4 + tig]);
            a[3] = __float_as_uint(Qs[(m0 + 8 + gr) * AQSTR + k0 + 4 + tig]);
#pragma unroll
            for (int ni = 0; ni < 8; ni++) {
                unsigned bfr[2];
                bfr[0] = __float_as_uint(Ks[(ni * 8 + gr) * AQSTR + k0 + tig]);
                bfr[1] = __float_as_uint(Ks[(ni * 8 + gr) * AQSTR + k0 + 4 + tig]);
                mma_tf32(sa[ni], a, bfr);
            }
        }

        // causal mask (only last two k-tiles can intersect the diagonal)
        if (kt >= 2 * qi) {
            int r0 = qbase + m0 + gr, r1 = r0 + 8;
#pragma unroll
            for (int ni = 0; ni < 8; ni++) {
                int c0 = kt * 64 + ni * 8 + 2 * tig;
                if (c0     > r0) sa[ni][0] = -INFINITY;
                if (c0 + 1 > r0) sa[ni][1] = -INFINITY;
                if (c0     > r1) sa[ni][2] = -INFINITY;
                if (c0 + 1 > r1) sa[ni][3] = -INFINITY;
            }
        }

        // warp-local online softmax (rows gr and gr+8)
        float mx0 = -INFINITY, mx1 = -INFINITY;
#pragma unroll
        for (int ni = 0; ni < 8; ni++) {
            mx0 = fmaxf(mx0, fmaxf(sa[ni][0], sa[ni][1]));
            mx1 = fmaxf(mx1, fmaxf(sa[ni][2], sa[ni][3]));
        }
        mx0 = fmaxf(mx0, __shfl_xor_sync(0xffffffffu, mx0, 1));
        mx0 = fmaxf(mx0, __shfl_xor_sync(0xffffffffu, mx0, 2));
        mx1 = fmaxf(mx1, __shfl_xor_sync(0xffffffffu, mx1, 1));
        mx1 = fmaxf(mx1, __shfl_xor_sync(0xffffffffu, mx1, 2));
        float mn0 = fmaxf(mo0, mx0), mn1 = fmaxf(mo1, mx1);
        float cf0 = (mo0 == -INFINITY) ? 0.f : __expf(mo0 - mn0);
        float cf1 = (mo1 == -INFINITY) ? 0.f : __expf(mo1 - mn1);

        unsigned ph[8][2];
        float s0 = 0.f, s1 = 0.f;
#pragma unroll
        for (int ni = 0; ni < 8; ni++) {
            float p0 = (sa[ni][0] == -INFINITY) ? 0.f : __expf(sa[ni][0] - mn0);
            float p1 = (sa[ni][1] == -INFINITY) ? 0.f : __expf(sa[ni][1] - mn0);
            float p2 = (sa[ni][2] == -INFINITY) ? 0.f : __expf(sa[ni][2] - mn1);
            float p3 = (sa[ni][3] == -INFINITY) ? 0.f : __expf(sa[ni][3] - mn1);
            s0 += p0 + p1; s1 += p2 + p3;
            ph[ni][0] = pack_h2(p0, p1);
            ph[ni][1] = pack_h2(p2, p3);
        }
        s0 += __shfl_xor_sync(0xffffffffu, s0, 1);
        s0 += __shfl_xor_sync(0xffffffffu, s0, 2);
        s1 += __shfl_xor_sync(0xffffffffu, s1, 1);
        s1 += __shfl_xor_sync(0xffffffffu, s1, 2);
        lr0 = lr0 * cf0 + s0; mo0 = mn0;
        lr1 = lr1 * cf1 + s1; mo1 = mn1;

        // O rescale
#pragma unroll
        for (int ni = 0; ni < 16; ni++) {
            oacc[ni][0] *= cf0; oacc[ni][1] *= cf0;
            oacc[ni][2] *= cf1; oacc[ni][3] *= cf1;
        }

        // P A-frags (fp16): frag j covers k cols 16j..16j+15
        unsigned pa[4][4];
#pragma unroll
        for (int j = 0; j < 4; j++) {
            pa[j][0] = ph[2 * j][0];
            pa[j][1] = ph[2 * j][1];
            pa[j][2] = ph[2 * j + 1][0];
            pa[j][3] = ph[2 * j + 1][1];
        }

        // O += P @ V (fp16), V b-frags via ldmatrix.x4.trans
#pragma unroll
        for (int jj = 0; jj < 2; jj++) {
            int vrow = 32 * jj + lane;
#pragma unroll
            for (int ni = 0; ni < 16; ni++) {
                unsigned d[4];
                ldsm_x4_trans(d, vbase + vrow * 272 + ni * 16);
                mma_f16(oacc[ni], pa[2 * jj],     d);       // d[0],d[1] = b-frag k16 #0
                mma_f16(oacc[ni], pa[2 * jj + 1], d + 2);   // d[2],d[3] = b-frag k16 #1
            }
        }
    }

    // epilogue: normalize, zero padded rows, write bf16 hi/lo (A operand of out-GEMM)
    {
        int len = g_len[b];
        int r0 = m0 + gr, r1 = m0 + 8 + gr;
        int t0 = qbase + r0, t1 = qbase + r1;
        float inv0 = (t0 < len) ? 1.0f / lr0 : 0.f;
        float inv1 = (t1 < len) ? 1.0f / lr1 : 0.f;
        size_t base0 = (((size_t)b * TT + t0) * CC + (size_t)h * DD) >> 1;
        size_t base1 = (((size_t)b * TT + t1) * CC + (size_t)h * DD) >> 1;
#pragma unroll
        for (int ni = 0; ni < 16; ni++) {
            int w = ni * 4 + tig;       // word index of col pair (2tig within n8 tile)
            float o0 = oacc[ni][0] * inv0, o1 = oacc[ni][1] * inv0;
            float o2 = oacc[ni][2] * inv1, o3 = oacc[ni][3] * inv1;
            float l0, l1, l2, l3;
            g_ah[base0 + w] = pack_hi(o0, o1, l0, l1);
            g_al[base0 + w] = pack_bf(l0, l1);
            g_ah[base1 + w] = pack_hi(o2, o3, l2, l3);
            g_al[base1 + w] = pack_bf(l2, l3);
        }
    }
}

// ---------------- launch ----------------
extern "C" void kernel_launch(void* const* d_in, const int* in_sizes, int n_in,
                              void* d_out, int out_size) {
    const float* x    = (const float*)d_in[0];
    const void*  mask = d_in[1];
    const float* Wqkv = (const float*)d_in[2];
    const float* Wout = (const float*)d_in[3];
    float* out = (float*)d_out;

    float* qkv;    cudaGetSymbolAddress((void**)&qkv,    g_qkv);
    unsigned *xh, *xl, *ah, *al, *wqh, *wql, *woh, *wol;
    cudaGetSymbolAddress((void**)&xh,  g_xh);
    cudaGetSymbolAddress((void**)&xl,  g_xl);
    cudaGetSymbolAddress((void**)&ah,  g_ah);
    cudaGetSymbolAddress((void**)&al,  g_al);
    cudaGetSymbolAddress((void**)&wqh, g_wqkvh);
    cudaGetSymbolAddress((void**)&wql, g_wqkvl);
    cudaGetSymbolAddress((void**)&woh, g_wouth);
    cudaGetSymbolAddress((void**)&wol, g_woutl);

    lengths_kernel<<<BB, 256>>>(mask);
    rope_table_kernel<<<(TT * 64 + 255) / 256, 256>>>();

    {
        size_t nw = (size_t)BT * CC / 2;
        split_a_kernel<<<(unsigned)((nw + 255) / 256), 256>>>(x, xh, xl, nw);
        size_t nq = (size_t)(CC / 2) * C3;
        split_b_kernel<<<(unsigned)((nq + 255) / 256), 256>>>(Wqkv, wqh, wql, CC, C3);
        size_t no = (size_t)(CC / 2) * CC;
        split_b_kernel<<<(unsigned)((no + 255) / 256), 256>>>(Wout, woh, wol, CC, CC);
    }

    cudaFuncSetAttribute(gemm_bf16x3_kernel, cudaFuncAttributeMaxDynamicSharedMemorySize, GEMM_SMEM);

    // qkv = x @ Wqkv  (bf16x3; outputs tf32-rounded for attention)
    gemm_bf16x3_kernel<<<dim3(C3 / 128, BT / 128), 128, GEMM_SMEM>>>(
        xh, xl, wqh, wql, qkv, BT, C3, CC, 1);

    // RoPE in place on Q,K (tf32-rounded; Q pre-scaled by 1/sqrt(d))
    rope_apply_kernel<<<(BB * TT * 2 * HH * 64) / 256, 256>>>();

    // causal flash attention: warp-local softmax, fp16 P.V
    cudaFuncSetAttribute(attn_kernel, cudaFuncAttributeMaxDynamicSharedMemorySize, ATT_SMEM_BYTES);
    attn_kernel<<<dim3(TT / 128, BB * HH), 256, ATT_SMEM_BYTES>>>();

    // out = attn @ Wout  (bf16x3; fp32 output)
    gemm_bf16x3_kernel<<<dim3(CC / 128, BT / 128), 128, GEMM_SMEM>>>(
        ah, al, woh, wol, out, BT, CC, CC, 0);
}

// round 12
// speedup vs baseline: 1.1990x; 1.0390x over previous
#include <cuda_runtime.h>
#include <cuda_bf16.h>
#include <cuda_fp16.h>
#include <math.h>

#define BB 2
#define TT 2048
#define CC 2048
#define HH 16
#define DD 128
#define C3 (3*CC)
#define BT (BB*TT)

// ---------------- device scratch ----------------
__device__ float g_qkv[(size_t)BT * C3];               // fp32 qkv (GEMM1 out)
__device__ unsigned g_qkvh[(size_t)BT * (C3/2)];       // fp16 qkv (rope/scale/conv out)
__device__ unsigned g_xh[(size_t)BT * CC / 2];
__device__ unsigned g_xl[(size_t)BT * CC / 2];
__device__ unsigned g_ah[(size_t)BT * CC / 2];
__device__ unsigned g_al[(size_t)BT * CC / 2];
__device__ unsigned g_wqkvh[(size_t)(CC/2) * C3];
__device__ unsigned g_wqkvl[(size_t)(CC/2) * C3];
__device__ unsigned g_wouth[(size_t)(CC/2) * CC];
__device__ unsigned g_woutl[(size_t)(CC/2) * CC];
__device__ float g_cos[TT * 64];
__device__ float g_sin[TT * 64];
__device__ int   g_len[BB];

// ---------------- helpers ----------------
__device__ __forceinline__ unsigned smem_u32(const void* p) {
    return (unsigned)__cvta_generic_to_shared(p);
}
__device__ __forceinline__ void mma_bf16(float* d, const unsigned* a, const unsigned* b) {
    asm volatile(
        "mma.sync.aligned.m16n8k16.row.col.f32.bf16.bf16.f32 "
        "{%0,%1,%2,%3}, {%4,%5,%6,%7}, {%8,%9}, {%0,%1,%2,%3};"
        : "+f"(d[0]), "+f"(d[1]), "+f"(d[2]), "+f"(d[3])
        : "r"(a[0]), "r"(a[1]), "r"(a[2]), "r"(a[3]), "r"(b[0]), "r"(b[1]));
}
__device__ __forceinline__ void mma_f16(float* d, const unsigned* a, const unsigned* b) {
    asm volatile(
        "mma.sync.aligned.m16n8k16.row.col.f32.f16.f16.f32 "
        "{%0,%1,%2,%3}, {%4,%5,%6,%7}, {%8,%9}, {%0,%1,%2,%3};"
        : "+f"(d[0]), "+f"(d[1]), "+f"(d[2]), "+f"(d[3])
        : "r"(a[0]), "r"(a[1]), "r"(a[2]), "r"(a[3]), "r"(b[0]), "r"(b[1]));
}
__device__ __forceinline__ void ldsm_x4_trans(unsigned* d, unsigned addr) {
    asm volatile("ldmatrix.sync.aligned.m8n8.x4.trans.shared.b16 {%0,%1,%2,%3}, [%4];"
                 : "=r"(d[0]), "=r"(d[1]), "=r"(d[2]), "=r"(d[3]) : "r"(addr));
}
__device__ __forceinline__ unsigned pack_h2(float a, float b) {
    __half2 h = __floats2half2_rn(a, b);
    return *(unsigned*)&h;
}
__device__ __forceinline__ unsigned pack_hi(float v0, float v1, float &r0, float &r1) {
    __nv_bfloat16 h0 = __float2bfloat16(v0);
    __nv_bfloat16 h1 = __float2bfloat16(v1);
    r0 = v0 - __bfloat162float(h0);
    r1 = v1 - __bfloat162float(h1);
    unsigned u0 = __bfloat16_as_ushort(h0), u1 = __bfloat16_as_ushort(h1);
    return u0 | (u1 << 16);
}
__device__ __forceinline__ unsigned pack_bf(float v0, float v1) {
    unsigned u0 = __bfloat16_as_ushort(__float2bfloat16(v0));
    unsigned u1 = __bfloat16_as_ushort(__float2bfloat16(v1));
    return u0 | (u1 << 16);
}

// ================= merged prep kernel: splits + rope tables + lengths =============
#define NBLK_A 16384      // split x:    BT*CC/2 words
#define NBLK_B 24576      // split Wqkv: (CC/2)*C3 words
#define NBLK_C 8192       // split Wout: (CC/2)*CC words
#define NBLK_D 512        // rope tables
#define NBLK_E 2          // lengths
#define NBLK_PREP (NBLK_A + NBLK_B + NBLK_C + NBLK_D + NBLK_E)

__device__ __forceinline__ void split_b_elem(const float* __restrict__ W,
                                             unsigned* dh, unsigned* dl,
                                             int N, size_t idx) {
    int n = (int)(idx % N);
    int k2 = (int)(idx / N);
    float v0 = W[(size_t)(2 * k2) * N + n];
    float v1 = W[(size_t)(2 * k2 + 1) * N + n];
    float l0, l1;
    dh[idx] = pack_hi(v0, v1, l0, l1);
    dl[idx] = pack_bf(l0, l1);
}

__global__ void prep_kernel(const float* __restrict__ x, const void* __restrict__ mask,
                            const float* __restrict__ Wqkv, const float* __restrict__ Wout) {
    __shared__ int ssum[256];
    unsigned bi = blockIdx.x;
    int tid = threadIdx.x;
    if (bi < NBLK_A) {
        size_t w = (size_t)bi * 256 + tid;
        float2 v = *(const float2*)&x[w * 2];
        float l0, l1;
        g_xh[w] = pack_hi(v.x, v.y, l0, l1);
        g_xl[w] = pack_bf(l0, l1);
    } else if (bi < NBLK_A + NBLK_B) {
        size_t idx = (size_t)(bi - NBLK_A) * 256 + tid;
        split_b_elem(Wqkv, g_wqkvh, g_wqkvl, C3, idx);
    } else if (bi < NBLK_A + NBLK_B + NBLK_C) {
        size_t idx = (size_t)(bi - NBLK_A - NBLK_B) * 256 + tid;
        split_b_elem(Wout, g_wouth, g_woutl, CC, idx);
    } else if (bi < NBLK_A + NBLK_B + NBLK_C + NBLK_D) {
        int idx = (int)(bi - NBLK_A - NBLK_B - NBLK_C) * 256 + tid;
        int t = idx >> 6, i = idx & 63;
        float invf = (float)(1.0 / pow(10000.0, (double)i / 64.0));
        float ang = (float)t * invf;
        double a = (double)ang;
        g_cos[idx] = (float)cos(a);
        g_sin[idx] = (float)sin(a);
    } else {
        int b = (int)(bi - NBLK_A - NBLK_B - NBLK_C - NBLK_D);
        unsigned int w0 = *(const unsigned int*)mask;
        int cnt = 0;
        if (w0 == 0x01010101u) {
            const unsigned char* m = (const unsigned char*)mask + (size_t)b * TT;
            for (int i = tid; i < TT; i += 256) cnt += (m[i] != 0);
        } else if (w0 == 0x3F800000u) {
            const float* m = (const float*)mask + (size_t)b * TT;
            for (int i = tid; i < TT; i += 256) cnt += (m[i] != 0.0f);
        } else {
            const int* m = (const int*)mask + (size_t)b * TT;
            for (int i = tid; i < TT; i += 256) cnt += (m[i] != 0);
        }
        ssum[tid] = cnt;
        __syncthreads();
        for (int s = 128; s > 0; s >>= 1) {
            if (tid < s) ssum[tid] += ssum[tid + s];
            __syncthreads();
        }
        if (tid == 0) g_len[b] = ssum[0];
    }
}

// ========= RoPE (Q scaled) + V conversion: fp32 g_qkv -> fp16 g_qkvh =========
// qk part: idx in [0, BB*TT*2*HH*32): each thread rotates 2 pairs (4 elems -> 2 words)
// v part:  one word (2 elems) per thread.
#define ROPE_QK_THREADS (BB * TT * 2 * HH * 32)
#define ROPE_V_THREADS  ((size_t)BT * CC / 2)
#define ROPE_BLOCKS ((ROPE_QK_THREADS + (int)ROPE_V_THREADS) / 256)

__global__ void rope_fp16_kernel() {
    int idx = blockIdx.x * blockDim.x + threadIdx.x;
    if (idx < ROPE_QK_THREADS) {
        int i2 = idx & 31; int r = idx >> 5;
        int h = r & (HH - 1); r >>= 4;
        int w = r & 1; r >>= 1;
        int t = r & (TT - 1); r >>= 11;
        int b = r;
        size_t base = ((size_t)(b * TT + t)) * C3 + (size_t)w * CC + (size_t)h * DD;
        int i0 = 2 * i2;
        float c0 = g_cos[t * 64 + i0], s0 = g_sin[t * 64 + i0];
        float c1 = g_cos[t * 64 + i0 + 1], s1 = g_sin[t * 64 + i0 + 1];
        float xa0 = g_qkv[base + i0],      xa1 = g_qkv[base + i0 + 1];
        float xb0 = g_qkv[base + 64 + i0], xb1 = g_qkv[base + 64 + i0 + 1];
        float ya0 = xa0 * c0 - xb0 * s0;
        float ya1 = xa1 * c1 - xb1 * s1;
        float yb0 = xb0 * c0 + xa0 * s0;
        float yb1 = xb1 * c1 + xa1 * s1;
        if (w == 0) {
            const float scale = 0.08838834764831845f;
            ya0 *= scale; ya1 *= scale; yb0 *= scale; yb1 *= scale;
        }
        size_t whead = ((size_t)(b * TT + t)) * (C3/2) + (size_t)w * (CC/2) + (size_t)h * 64;
        g_qkvh[whead + i2]      = pack_h2(ya0, ya1);
        g_qkvh[whead + 32 + i2] = pack_h2(yb0, yb1);
    } else {
        size_t j = (size_t)(idx - ROPE_QK_THREADS);
        size_t tok = j / (CC / 2);
        int jc = (int)(j % (CC / 2));
        size_t src = tok * C3 + 2 * CC + 2 * jc;
        float v0 = g_qkv[src], v1 = g_qkv[src + 1];
        g_qkvh[tok * (C3/2) + 2 * (CC/2) + jc] = pack_h2(v0, v1);
    }
}

// ================= bf16x3 tensor-core GEMM (R6-proven config) ==============
#define KCB 32
#define ASTRW 20
#define BSTRW 136
#define ATILEW (128 * ASTRW)
#define BTILEW (16 * BSTRW)
#define GEMM_SMEM ((4 * ATILEW + 4 * BTILEW) * 4)

__device__ __forceinline__ void gemm_load_chunk_bf(
    unsigned* Ah, unsigned* Al, unsigned* Bh, unsigned* Bl,
    const unsigned* __restrict__ Agh, const unsigned* __restrict__ Agl,
    const unsigned* __restrict__ Bgh, const unsigned* __restrict__ Bgl,
    int row0, int col0, int kc, int K, int N, int tid)
{
    const int Kw = K >> 1;
#pragma unroll
    for (int i = 0; i < 4; i++) {
        int c = i * 128 + tid;
        int row = c >> 2, segw = (c & 3) << 2;
        size_t gsrc = (size_t)(row0 + row) * Kw + (kc >> 1) + segw;
        int dstw = row * ASTRW + segw;
        asm volatile("cp.async.cg.shared.global [%0], [%1], 16;"
                     :: "r"(smem_u32(Ah + dstw)), "l"(Agh + gsrc));
        asm volatile("cp.async.cg.shared.global [%0], [%1], 16;"
                     :: "r"(smem_u32(Al + dstw)), "l"(Agl + gsrc));
    }
#pragma unroll
    for (int i = 0; i < 4; i++) {
        int c = i * 128 + tid;
        int krow = c >> 5, segw = (c & 31) << 2;
        size_t gsrc = (size_t)((kc >> 1) + krow) * N + col0 + segw;
        int dstw = krow * BSTRW + segw;
        asm volatile("cp.async.cg.shared.global [%0], [%1], 16;"
                     :: "r"(smem_u32(Bh + dstw)), "l"(Bgh + gsrc));
        asm volatile("cp.async.cg.shared.global [%0], [%1], 16;"
                     :: "r"(smem_u32(Bl + dstw)), "l"(Bgl + gsrc));
    }
    asm volatile("cp.async.commit_group;");
}

__global__ __launch_bounds__(128, 2) void gemm_bf16x3_kernel(
    const unsigned* __restrict__ Agh, const unsigned* __restrict__ Agl,
    const unsigned* __restrict__ Bgh, const unsigned* __restrict__ Bgl,
    float* __restrict__ C, int M, int N, int K)
{
    extern __shared__ unsigned smw[];
    unsigned* Ah = smw;
    unsigned* Al = smw + 2 * ATILEW;
    unsigned* Bh = smw + 4 * ATILEW;
    unsigned* Bl = smw + 4 * ATILEW + 2 * BTILEW;

    const int tid  = threadIdx.x;
    const int lane = tid & 31, warp = tid >> 5;
    const int wr = warp >> 1, wc = warp & 1;
    const int gr = lane >> 2, tig = lane & 3;
    const int row0 = blockIdx.y * 128, col0 = blockIdx.x * 128;

    float acc[4][8][4];
#pragma unroll
    for (int mi = 0; mi < 4; mi++)
#pragma unroll
        for (int ni = 0; ni < 8; ni++)
#pragma unroll
            for (int r = 0; r < 4; r++) acc[mi][ni][r] = 0.f;

    const int nc = K / KCB;
    gemm_load_chunk_bf(Ah, Al, Bh, Bl, Agh, Agl, Bgh, Bgl, row0, col0, 0, K, N, tid);

    for (int c = 0; c < nc; c++) {
        if (c + 1 < nc) {
            int nb = (c + 1) & 1;
            gemm_load_chunk_bf(Ah + nb * ATILEW, Al + nb * ATILEW,
                               Bh + nb * BTILEW, Bl + nb * BTILEW,
                               Agh, Agl, Bgh, Bgl, row0, col0, (c + 1) * KCB, K, N, tid);
            asm volatile("cp.async.wait_group 1;");
        } else {
            asm volatile("cp.async.wait_group 0;");
        }
        __syncthreads();

        const unsigned* ah = Ah + (c & 1) * ATILEW;
        const unsigned* al = Al + (c & 1) * ATILEW;
        const unsigned* bh = Bh + (c & 1) * BTILEW;
        const unsigned* bl = Bl + (c & 1) * BTILEW;

#pragma unroll
        for (int s = 0; s < 2; s++) {
            const int kw = s * 8;
            unsigned afh[4][4], afl[4][4], bfh[8][2], bfl[8][2];
#pragma unroll
            for (int mi = 0; mi < 4; mi++) {
                int m0 = wr * 64 + mi * 16;
                int w0 = (m0 + gr) * ASTRW + kw + tig;
                int w1 = (m0 + 8 + gr) * ASTRW + kw + tig;
                afh[mi][0] = ah[w0];     afh[mi][1] = ah[w1];
                afh[mi][2] = ah[w0 + 4]; afh[mi][3] = ah[w1 + 4];
                afl[mi][0] = al[w0];     afl[mi][1] = al[w1];
                afl[mi][2] = al[w0 + 4]; afl[mi][3] = al[w1 + 4];
            }
#pragma unroll
            for (int ni = 0; ni < 8; ni++) {
                int n0 = wc * 64 + ni * 8;
                int w0 = (kw + tig) * BSTRW + n0 + gr;
                int w1 = (kw + 4 + tig) * BSTRW + n0 + gr;
                bfh[ni][0] = bh[w0]; bfh[ni][1] = bh[w1];
                bfl[ni][0] = bl[w0]; bfl[ni][1] = bl[w1];
            }
#pragma unroll
            for (int mi = 0; mi < 4; mi++)
#pragma unroll
                for (int ni = 0; ni < 8; ni++) {
                    mma_bf16(acc[mi][ni], afl[mi], bfh[ni]);
                    mma_bf16(acc[mi][ni], afh[mi], bfl[ni]);
                    mma_bf16(acc[mi][ni], afh[mi], bfh[ni]);
                }
        }
        __syncthreads();
    }

#pragma unroll
    for (int mi = 0; mi < 4; mi++) {
        int m0 = row0 + wr * 64 + mi * 16;
#pragma unroll
        for (int ni = 0; ni < 8; ni++) {
            int n0 = col0 + wc * 64 + ni * 8 + 2 * tig;
            float* p0 = C + (size_t)(m0 + gr) * N + n0;
            float* p1 = C + (size_t)(m0 + 8 + gr) * N + n0;
            p0[0] = acc[mi][ni][0]; p0[1] = acc[mi][ni][1];
            p1[0] = acc[mi][ni][2]; p1[1] = acc[mi][ni][3];
        }
    }
}

// ====== FA-2 attention, all-fp16 operands: BLK_M=128, 8 warps x (m16 x n64) ======
#define HSTR 68                         // fp16 row stride in words (128 halves + pad)
#define SMW_Q 0                         // [128][HSTR]
#define SMW_K (128 * HSTR)              // [64][HSTR]
#define SMW_V (SMW_K + 64 * HSTR)       // [64][HSTR]
#define ATT_SMEM_W (SMW_V + 64 * HSTR)
#define ATT_SMEM_BYTES (ATT_SMEM_W * 4)

__global__ __launch_bounds__(256, 1) void attn_kernel() {
    extern __shared__ unsigned smu[];
    unsigned* Qw = smu + SMW_Q;
    unsigned* Kw = smu + SMW_K;
    unsigned* Vw = smu + SMW_V;
    const unsigned vbase = smem_u32(smu + SMW_V);

    const int tid = threadIdx.x;
    const int lane = tid & 31, wid = tid >> 5;
    const int gr = lane >> 2, tig = lane & 3;
    const int m0 = wid * 16;
    const int bh = blockIdx.y;
    const int b = bh >> 4, h = bh & 15;
    const int qi = (int)gridDim.x - 1 - (int)blockIdx.x;   // heavy tiles first
    const int qbase = qi * 128;

    const unsigned* Qg = g_qkvh + (size_t)b * TT * (C3/2) + (size_t)h * 64;
    const unsigned* Kg = Qg + (CC/2);
    const unsigned* Vg = Qg + 2 * (CC/2);

    // Q tile load (128 rows x 64 words) via cp.async: 2048 chunks of 16B
#pragma unroll
    for (int l = 0; l < 8; l++) {
        int chunk = l * 256 + tid;
        int row = chunk >> 4, c4 = (chunk & 15) << 2;
        asm volatile("cp.async.cg.shared.global [%0], [%1], 16;"
                     :: "r"(smem_u32(Qw + row * HSTR + c4)),
                        "l"(Qg + (size_t)(qbase + row) * (C3/2) + c4));
    }
    asm volatile("cp.async.commit_group;" ::: "memory");

    float mo0 = -INFINITY, mo1 = -INFINITY, lr0 = 0.f, lr1 = 0.f;
    float oacc[16][4];
#pragma unroll
    for (int ni = 0; ni < 16; ni++)
#pragma unroll
        for (int r = 0; r < 4; r++) oacc[ni][r] = 0.f;

    const int nkt = 2 * qi + 2;
    for (int kt = 0; kt < nkt; kt++) {
        // K,V tile loads (64 rows x 64 words each): 1024 chunks each
#pragma unroll
        for (int l = 0; l < 4; l++) {
            int chunk = l * 256 + tid;
            int row = chunk >> 4, c4 = (chunk & 15) << 2;
            size_t gofs = (size_t)(kt * 64 + row) * (C3/2) + c4;
            asm volatile("cp.async.cg.shared.global [%0], [%1], 16;"
                         :: "r"(smem_u32(Kw + row * HSTR + c4)), "l"(Kg + gofs));
            asm volatile("cp.async.cg.shared.global [%0], [%1], 16;"
                         :: "r"(smem_u32(Vw + row * HSTR + c4)), "l"(Vg + gofs));
        }
        asm volatile("cp.async.commit_group;" ::: "memory");
        asm volatile("cp.async.wait_group 0;" ::: "memory");
        __syncthreads();

        // S = Q K^T : m16 x n64, fp16 (8 k16-steps)
        float sa[8][4];
#pragma unroll
        for (int ni = 0; ni < 8; ni++)
#pragma unroll
            for (int r = 0; r < 4; r++) sa[ni][r] = 0.f;

#pragma unroll
        for (int ks = 0; ks < 8; ks++) {
            const int k0 = ks * 8;     // word offset of this k16 step
            unsigned a[4];
            a[0] = Qw[(m0 + gr)     * HSTR + k0 + tig];
            a[1] = Qw[(m0 + 8 + gr) * HSTR + k0 + tig];
            a[2] = Qw[(m0 + gr)     * HSTR + k0 + 4 + tig];
            a[3] = Qw[(m0 + 8 + gr) * HSTR + k0 + 4 + tig];
#pragma unroll
            for (int ni = 0; ni < 8; ni++) {
                unsigned bfr[2];
                bfr[0] = Kw[(ni * 8 + gr) * HSTR + k0 + tig];
                bfr[1] = Kw[(ni * 8 + gr) * HSTR + k0 + 4 + tig];
                mma_f16(sa[ni], a, bfr);
            }
        }

        // causal mask (only last two k-tiles can intersect the diagonal)
        if (kt >= 2 * qi) {
            int r0 = qbase + m0 + gr, r1 = r0 + 8;
#pragma unroll
            for (int ni = 0; ni < 8; ni++) {
                int c0 = kt * 64 + ni * 8 + 2 * tig;
                if (c0     > r0) sa[ni][0] = -INFINITY;
                if (c0 + 1 > r0) sa[ni][1] = -INFINITY;
                if (c0     > r1) sa[ni][2] = -INFINITY;
                if (c0 + 1 > r1) sa[ni][3] = -INFINITY;
            }
        }

        // warp-local online softmax
        float mx0 = -INFINITY, mx1 = -INFINITY;
#pragma unroll
        for (int ni = 0; ni < 8; ni++) {
            mx0 = fmaxf(mx0, fmaxf(sa[ni][0], sa[ni][1]));
            mx1 = fmaxf(mx1, fmaxf(sa[ni][2], sa[ni][3]));
        }
        mx0 = fmaxf(mx0, __shfl_xor_sync(0xffffffffu, mx0, 1));
        mx0 = fmaxf(mx0, __shfl_xor_sync(0xffffffffu, mx0, 2));
        mx1 = fmaxf(mx1, __shfl_xor_sync(0xffffffffu, mx1, 1));
        mx1 = fmaxf(mx1, __shfl_xor_sync(0xffffffffu, mx1, 2));
        float mn0 = fmaxf(mo0, mx0), mn1 = fmaxf(mo1, mx1);
        float cf0 = (mo0 == -INFINITY) ? 0.f : __expf(mo0 - mn0);
        float cf1 = (mo1 == -INFINITY) ? 0.f : __expf(mo1 - mn1);

        unsigned ph[8][2];
        float s0 = 0.f, s1 = 0.f;
#pragma unroll
        for (int ni = 0; ni < 8; ni++) {
            float p0 = (sa[ni][0] == -INFINITY) ? 0.f : __expf(sa[ni][0] - mn0);
            float p1 = (sa[ni][1] == -INFINITY) ? 0.f : __expf(sa[ni][1] - mn0);
            float p2 = (sa[ni][2] == -INFINITY) ? 0.f : __expf(sa[ni][2] - mn1);
            float p3 = (sa[ni][3] == -INFINITY) ? 0.f : __expf(sa[ni][3] - mn1);
            s0 += p0 + p1; s1 += p2 + p3;
            ph[ni][0] = pack_h2(p0, p1);
            ph[ni][1] = pack_h2(p2, p3);
        }
        s0 += __shfl_xor_sync(0xffffffffu, s0, 1);
        s0 += __shfl_xor_sync(0xffffffffu, s0, 2);
        s1 += __shfl_xor_sync(0xffffffffu, s1, 1);
        s1 += __shfl_xor_sync(0xffffffffu, s1, 2);
        lr0 = lr0 * cf0 + s0; mo0 = mn0;
        lr1 = lr1 * cf1 + s1; mo1 = mn1;

#pragma unroll
        for (int ni = 0; ni < 16; ni++) {
            oacc[ni][0] *= cf0; oacc[ni][1] *= cf0;
            oacc[ni][2] *= cf1; oacc[ni][3] *= cf1;
        }

        unsigned pa[4][4];
#pragma unroll
        for (int j = 0; j < 4; j++) {
            pa[j][0] = ph[2 * j][0];
            pa[j][1] = ph[2 * j][1];
            pa[j][2] = ph[2 * j + 1][0];
            pa[j][3] = ph[2 * j + 1][1];
        }

        // O += P @ V (fp16), V b-frags via ldmatrix.x4.trans
#pragma unroll
        for (int jj = 0; jj < 2; jj++) {
            int vrow = 32 * jj + lane;
#pragma unroll
            for (int ni = 0; ni < 16; ni++) {
                unsigned d[4];
                ldsm_x4_trans(d, vbase + vrow * (HSTR * 4) + ni * 16);
                mma_f16(oacc[ni], pa[2 * jj],     d);
                mma_f16(oacc[ni], pa[2 * jj + 1], d + 2);
            }
        }
        __syncthreads();   // K/V reads done before next tile overwrites
    }

    // epilogue: normalize, zero padded rows, write bf16 hi/lo (A operand of out-GEMM)
    {
        int len = g_len[b];
        int r0 = m0 + gr, r1 = m0 + 8 + gr;
        int t0 = qbase + r0, t1 = qbase + r1;
        float inv0 = (t0 < len) ? 1.0f / lr0 : 0.f;
        float inv1 = (t1 < len) ? 1.0f / lr1 : 0.f;
        size_t base0 = (((size_t)b * TT + t0) * CC + (size_t)h * DD) >> 1;
        size_t base1 = (((size_t)b * TT + t1) * CC + (size_t)h * DD) >> 1;
#pragma unroll
        for (int ni = 0; ni < 16; ni++) {
            int w = ni * 4 + tig;
            float o0 = oacc[ni][0] * inv0, o1 = oacc[ni][1] * inv0;
            float o2 = oacc[ni][2] * inv1, o3 = oacc[ni][3] * inv1;
            float l0, l1, l2, l3;
            g_ah[base0 + w] = pack_hi(o0, o1, l0, l1);
            g_al[base0 + w] = pack_bf(l0, l1);
            g_ah[base1 + w] = pack_hi(o2, o3, l2, l3);
            g_al[base1 + w] = pack_bf(l2, l3);
        }
    }
}

// ---------------- launch ----------------
extern "C" void kernel_launch(void* const* d_in, const int* in_sizes, int n_in,
                              void* d_out, int out_size) {
    const float* x    = (const float*)d_in[0];
    const void*  mask = d_in[1];
    const float* Wqkv = (const float*)d_in[2];
    const float* Wout = (const float*)d_in[3];
    float* out = (float*)d_out;

    float* qkv;    cudaGetSymbolAddress((void**)&qkv,    g_qkv);
    unsigned *xh, *xl, *ah, *al, *wqh, *wql, *woh, *wol;
    cudaGetSymbolAddress((void**)&xh,  g_xh);
    cudaGetSymbolAddress((void**)&xl,  g_xl);
    cudaGetSymbolAddress((void**)&ah,  g_ah);
    cudaGetSymbolAddress((void**)&al,  g_al);
    cudaGetSymbolAddress((void**)&wqh, g_wqkvh);
    cudaGetSymbolAddress((void**)&wql, g_wqkvl);
    cudaGetSymbolAddress((void**)&woh, g_wouth);
    cudaGetSymbolAddress((void**)&wol, g_woutl);

    // merged prep: splits + rope tables + lengths (all independent)
    prep_kernel<<<NBLK_PREP, 256>>>(x, mask, Wqkv, Wout);

    cudaFuncSetAttribute(gemm_bf16x3_kernel, cudaFuncAttributeMaxDynamicSharedMemorySize, GEMM_SMEM);

    // qkv = x @ Wqkv  (bf16x3, fp32 out)
    gemm_bf16x3_kernel<<<dim3(C3 / 128, BT / 128), 128, GEMM_SMEM>>>(
        xh, xl, wqh, wql, qkv, BT, C3, CC);

    // RoPE q,k (scaled, fp16) + V fp16 conversion
    rope_fp16_kernel<<<ROPE_BLOCKS, 256>>>();

    // causal flash attention (all-fp16 operands, warp-local softmax)
    cudaFuncSetAttribute(attn_kernel, cudaFuncAttributeMaxDynamicSharedMemorySize, ATT_SMEM_BYTES);
    attn_kernel<<<dim3(TT / 128, BB * HH), 256, ATT_SMEM_BYTES>>>();

    // out = attn @ Wout  (bf16x3, fp32 out)
    gemm_bf16x3_kernel<<<dim3(CC / 128, BT / 128), 128, GEMM_SMEM>>>(
        ah, al, woh, wol, out, BT, CC, CC);
}

// round 13
// speedup vs baseline: 1.4821x; 1.2361x over previous
#include <cuda_runtime.h>
#include <cuda_bf16.h>
#include <cuda_fp16.h>
#include <math.h>

#define BB 2
#define TT 2048
#define CC 2048
#define HH 16
#define DD 128
#define C3 (3*CC)
#define BT (BB*TT)

// ---------------- device scratch ----------------
__device__ float g_qkv[(size_t)BT * C3];               // fp32 qkv (GEMM1 out)
__device__ unsigned g_qkvh[(size_t)BT * (C3/2)];       // fp16 qkv (rope/scale/conv out)
__device__ unsigned g_xh[(size_t)BT * CC / 2];
__device__ unsigned g_xl[(size_t)BT * CC / 2];
__device__ unsigned g_ah[(size_t)BT * CC / 2];
__device__ unsigned g_al[(size_t)BT * CC / 2];
__device__ unsigned g_wqkvh[(size_t)(CC/2) * C3];
__device__ unsigned g_wqkvl[(size_t)(CC/2) * C3];
__device__ unsigned g_wouth[(size_t)(CC/2) * CC];
__device__ unsigned g_woutl[(size_t)(CC/2) * CC];
__device__ float g_cos[TT * 64];
__device__ float g_sin[TT * 64];
__device__ int   g_len[BB];

// ---------------- helpers ----------------
__device__ __forceinline__ unsigned smem_u32(const void* p) {
    return (unsigned)__cvta_generic_to_shared(p);
}
__device__ __forceinline__ void mma_bf16(float* d, const unsigned* a, const unsigned* b) {
    asm volatile(
        "mma.sync.aligned.m16n8k16.row.col.f32.bf16.bf16.f32 "
        "{%0,%1,%2,%3}, {%4,%5,%6,%7}, {%8,%9}, {%0,%1,%2,%3};"
        : "+f"(d[0]), "+f"(d[1]), "+f"(d[2]), "+f"(d[3])
        : "r"(a[0]), "r"(a[1]), "r"(a[2]), "r"(a[3]), "r"(b[0]), "r"(b[1]));
}
__device__ __forceinline__ void mma_f16(float* d, const unsigned* a, const unsigned* b) {
    asm volatile(
        "mma.sync.aligned.m16n8k16.row.col.f32.f16.f16.f32 "
        "{%0,%1,%2,%3}, {%4,%5,%6,%7}, {%8,%9}, {%0,%1,%2,%3};"
        : "+f"(d[0]), "+f"(d[1]), "+f"(d[2]), "+f"(d[3])
        : "r"(a[0]), "r"(a[1]), "r"(a[2]), "r"(a[3]), "r"(b[0]), "r"(b[1]));
}
__device__ __forceinline__ void ldsm_x4_trans(unsigned* d, unsigned addr) {
    asm volatile("ldmatrix.sync.aligned.m8n8.x4.trans.shared.b16 {%0,%1,%2,%3}, [%4];"
                 : "=r"(d[0]), "=r"(d[1]), "=r"(d[2]), "=r"(d[3]) : "r"(addr));
}
__device__ __forceinline__ unsigned pack_h2(float a, float b) {
    __half2 h = __floats2half2_rn(a, b);
    return *(unsigned*)&h;
}
__device__ __forceinline__ unsigned pack_hi(float v0, float v1, float &r0, float &r1) {
    __nv_bfloat16 h0 = __float2bfloat16(v0);
    __nv_bfloat16 h1 = __float2bfloat16(v1);
    r0 = v0 - __bfloat162float(h0);
    r1 = v1 - __bfloat162float(h1);
    unsigned u0 = __bfloat16_as_ushort(h0), u1 = __bfloat16_as_ushort(h1);
    return u0 | (u1 << 16);
}
__device__ __forceinline__ unsigned pack_bf(float v0, float v1) {
    unsigned u0 = __bfloat16_as_ushort(__float2bfloat16(v0));
    unsigned u1 = __bfloat16_as_ushort(__float2bfloat16(v1));
    return u0 | (u1 << 16);
}

// ================= merged prep kernel: splits + rope tables + lengths =============
#define NBLK_A 16384
#define NBLK_B 24576
#define NBLK_C 8192
#define NBLK_D 512
#define NBLK_E 2
#define NBLK_PREP (NBLK_A + NBLK_B + NBLK_C + NBLK_D + NBLK_E)

__device__ __forceinline__ void split_b_elem(const float* __restrict__ W,
                                             unsigned* dh, unsigned* dl,
                                             int N, size_t idx) {
    int n = (int)(idx % N);
    int k2 = (int)(idx / N);
    float v0 = W[(size_t)(2 * k2) * N + n];
    float v1 = W[(size_t)(2 * k2 + 1) * N + n];
    float l0, l1;
    dh[idx] = pack_hi(v0, v1, l0, l1);
    dl[idx] = pack_bf(l0, l1);
}

__global__ void prep_kernel(const float* __restrict__ x, const void* __restrict__ mask,
                            const float* __restrict__ Wqkv, const float* __restrict__ Wout) {
    __shared__ int ssum[256];
    unsigned bi = blockIdx.x;
    int tid = threadIdx.x;
    if (bi < NBLK_A) {
        size_t w = (size_t)bi * 256 + tid;
        float2 v = *(const float2*)&x[w * 2];
        float l0, l1;
        g_xh[w] = pack_hi(v.x, v.y, l0, l1);
        g_xl[w] = pack_bf(l0, l1);
    } else if (bi < NBLK_A + NBLK_B) {
        size_t idx = (size_t)(bi - NBLK_A) * 256 + tid;
        split_b_elem(Wqkv, g_wqkvh, g_wqkvl, C3, idx);
    } else if (bi < NBLK_A + NBLK_B + NBLK_C) {
        size_t idx = (size_t)(bi - NBLK_A - NBLK_B) * 256 + tid;
        split_b_elem(Wout, g_wouth, g_woutl, CC, idx);
    } else if (bi < NBLK_A + NBLK_B + NBLK_C + NBLK_D) {
        int idx = (int)(bi - NBLK_A - NBLK_B - NBLK_C) * 256 + tid;
        int t = idx >> 6, i = idx & 63;
        float invf = (float)(1.0 / pow(10000.0, (double)i / 64.0));
        float ang = (float)t * invf;
        double a = (double)ang;
        g_cos[idx] = (float)cos(a);
        g_sin[idx] = (float)sin(a);
    } else {
        int b = (int)(bi - NBLK_A - NBLK_B - NBLK_C - NBLK_D);
        unsigned int w0 = *(const unsigned int*)mask;
        int cnt = 0;
        if (w0 == 0x01010101u) {
            const unsigned char* m = (const unsigned char*)mask + (size_t)b * TT;
            for (int i = tid; i < TT; i += 256) cnt += (m[i] != 0);
        } else if (w0 == 0x3F800000u) {
            const float* m = (const float*)mask + (size_t)b * TT;
            for (int i = tid; i < TT; i += 256) cnt += (m[i] != 0.0f);
        } else {
            const int* m = (const int*)mask + (size_t)b * TT;
            for (int i = tid; i < TT; i += 256) cnt += (m[i] != 0);
        }
        ssum[tid] = cnt;
        __syncthreads();
        for (int s = 128; s > 0; s >>= 1) {
            if (tid < s) ssum[tid] += ssum[tid + s];
            __syncthreads();
        }
        if (tid == 0) g_len[b] = ssum[0];
    }
}

// ========= RoPE (Q scaled) + V conversion: fp32 g_qkv -> fp16 g_qkvh =========
#define ROPE_QK_THREADS (BB * TT * 2 * HH * 32)
#define ROPE_V_THREADS  ((size_t)BT * CC / 2)
#define ROPE_BLOCKS ((ROPE_QK_THREADS + (int)ROPE_V_THREADS) / 256)

__global__ void rope_fp16_kernel() {
    int idx = blockIdx.x * blockDim.x + threadIdx.x;
    if (idx < ROPE_QK_THREADS) {
        int i2 = idx & 31; int r = idx >> 5;
        int h = r & (HH - 1); r >>= 4;
        int w = r & 1; r >>= 1;
        int t = r & (TT - 1); r >>= 11;
        int b = r;
        if (t >= g_len[b]) return;                      // dead row (never read)
        size_t base = ((size_t)(b * TT + t)) * C3 + (size_t)w * CC + (size_t)h * DD;
        int i0 = 2 * i2;
        float c0 = g_cos[t * 64 + i0], s0 = g_sin[t * 64 + i0];
        float c1 = g_cos[t * 64 + i0 + 1], s1 = g_sin[t * 64 + i0 + 1];
        float xa0 = g_qkv[base + i0],      xa1 = g_qkv[base + i0 + 1];
        float xb0 = g_qkv[base + 64 + i0], xb1 = g_qkv[base + 64 + i0 + 1];
        float ya0 = xa0 * c0 - xb0 * s0;
        float ya1 = xa1 * c1 - xb1 * s1;
        float yb0 = xb0 * c0 + xa0 * s0;
        float yb1 = xb1 * c1 + xa1 * s1;
        if (w == 0) {
            const float scale = 0.08838834764831845f;
            ya0 *= scale; ya1 *= scale; yb0 *= scale; yb1 *= scale;
        }
        size_t whead = ((size_t)(b * TT + t)) * (C3/2) + (size_t)w * (CC/2) + (size_t)h * 64;
        g_qkvh[whead + i2]      = pack_h2(ya0, ya1);
        g_qkvh[whead + 32 + i2] = pack_h2(yb0, yb1);
    } else {
        size_t j = (size_t)(idx - ROPE_QK_THREADS);
        size_t tok = j / (CC / 2);
        int jc = (int)(j % (CC / 2));
        int b = (int)(tok / TT), t = (int)(tok % TT);
        if (t >= g_len[b]) return;                      // dead row
        size_t src = tok * C3 + 2 * CC + 2 * jc;
        float v0 = g_qkv[src], v1 = g_qkv[src + 1];
        g_qkvh[tok * (C3/2) + 2 * (CC/2) + jc] = pack_h2(v0, v1);
    }
}

// ================= bf16x3 tensor-core GEMM (R6-proven config) ==============
// skip_mode: 0=none, 1=skip dead row-tiles silently, 2=skip + write zeros
#define KCB 32
#define ASTRW 20
#define BSTRW 136
#define ATILEW (128 * ASTRW)
#define BTILEW (16 * BSTRW)
#define GEMM_SMEM ((4 * ATILEW + 4 * BTILEW) * 4)

__device__ __forceinline__ void gemm_load_chunk_bf(
    unsigned* Ah, unsigned* Al, unsigned* Bh, unsigned* Bl,
    const unsigned* __restrict__ Agh, const unsigned* __restrict__ Agl,
    const unsigned* __restrict__ Bgh, const unsigned* __restrict__ Bgl,
    int row0, int col0, int kc, int K, int N, int tid)
{
    const int Kw = K >> 1;
#pragma unroll
    for (int i = 0; i < 4; i++) {
        int c = i * 128 + tid;
        int row = c >> 2, segw = (c & 3) << 2;
        size_t gsrc = (size_t)(row0 + row) * Kw + (kc >> 1) + segw;
        int dstw = row * ASTRW + segw;
        asm volatile("cp.async.cg.shared.global [%0], [%1], 16;"
                     :: "r"(smem_u32(Ah + dstw)), "l"(Agh + gsrc));
        asm volatile("cp.async.cg.shared.global [%0], [%1], 16;"
                     :: "r"(smem_u32(Al + dstw)), "l"(Agl + gsrc));
    }
#pragma unroll
    for (int i = 0; i < 4; i++) {
        int c = i * 128 + tid;
        int krow = c >> 5, segw = (c & 31) << 2;
        size_t gsrc = (size_t)((kc >> 1) + krow) * N + col0 + segw;
        int dstw = krow * BSTRW + segw;
        asm volatile("cp.async.cg.shared.global [%0], [%1], 16;"
                     :: "r"(smem_u32(Bh + dstw)), "l"(Bgh + gsrc));
        asm volatile("cp.async.cg.shared.global [%0], [%1], 16;"
                     :: "r"(smem_u32(Bl + dstw)), "l"(Bgl + gsrc));
    }
    asm volatile("cp.async.commit_group;");
}

__global__ __launch_bounds__(128, 2) void gemm_bf16x3_kernel(
    const unsigned* __restrict__ Agh, const unsigned* __restrict__ Agl,
    const unsigned* __restrict__ Bgh, const unsigned* __restrict__ Bgl,
    float* __restrict__ C, int M, int N, int K, int skip_mode)
{
    extern __shared__ unsigned smw[];
    unsigned* Ah = smw;
    unsigned* Al = smw + 2 * ATILEW;
    unsigned* Bh = smw + 4 * ATILEW;
    unsigned* Bl = smw + 4 * ATILEW + 2 * BTILEW;

    const int tid  = threadIdx.x;
    const int lane = tid & 31, warp = tid >> 5;
    const int wr = warp >> 1, wc = warp & 1;
    const int gr = lane >> 2, tig = lane & 3;
    const int row0 = blockIdx.y * 128, col0 = blockIdx.x * 128;

    if (skip_mode) {
        int lb = g_len[row0 / TT];
        if ((row0 % TT) >= lb) {
            if (skip_mode == 2) {
                // reference zeroes these rows after Wout: write zeros
#pragma unroll
                for (int mi = 0; mi < 4; mi++) {
                    int m0 = row0 + wr * 64 + mi * 16;
#pragma unroll
                    for (int ni = 0; ni < 8; ni++) {
                        int n0 = col0 + wc * 64 + ni * 8 + 2 * tig;
                        float* p0 = C + (size_t)(m0 + gr) * N + n0;
                        float* p1 = C + (size_t)(m0 + 8 + gr) * N + n0;
                        p0[0] = 0.f; p0[1] = 0.f;
                        p1[0] = 0.f; p1[1] = 0.f;
                    }
                }
            }
            return;
        }
    }

    float acc[4][8][4];
#pragma unroll
    for (int mi = 0; mi < 4; mi++)
#pragma unroll
        for (int ni = 0; ni < 8; ni++)
#pragma unroll
            for (int r = 0; r < 4; r++) acc[mi][ni][r] = 0.f;

    const int nc = K / KCB;
    gemm_load_chunk_bf(Ah, Al, Bh, Bl, Agh, Agl, Bgh, Bgl, row0, col0, 0, K, N, tid);

    for (int c = 0; c < nc; c++) {
        if (c + 1 < nc) {
            int nb = (c + 1) & 1;
            gemm_load_chunk_bf(Ah + nb * ATILEW, Al + nb * ATILEW,
                               Bh + nb * BTILEW, Bl + nb * BTILEW,
                               Agh, Agl, Bgh, Bgl, row0, col0, (c + 1) * KCB, K, N, tid);
            asm volatile("cp.async.wait_group 1;");
        } else {
            asm volatile("cp.async.wait_group 0;");
        }
        __syncthreads();

        const unsigned* ah = Ah + (c & 1) * ATILEW;
        const unsigned* al = Al + (c & 1) * ATILEW;
        const unsigned* bh = Bh + (c & 1) * BTILEW;
        const unsigned* bl = Bl + (c & 1) * BTILEW;

#pragma unroll
        for (int s = 0; s < 2; s++) {
            const int kw = s * 8;
            unsigned afh[4][4], afl[4][4], bfh[8][2], bfl[8][2];
#pragma unroll
            for (int mi = 0; mi < 4; mi++) {
                int m0 = wr * 64 + mi * 16;
                int w0 = (m0 + gr) * ASTRW + kw + tig;
                int w1 = (m0 + 8 + gr) * ASTRW + kw + tig;
                afh[mi][0] = ah[w0];     afh[mi][1] = ah[w1];
                afh[mi][2] = ah[w0 + 4]; afh[mi][3] = ah[w1 + 4];
                afl[mi][0] = al[w0];     afl[mi][1] = al[w1];
                afl[mi][2] = al[w0 + 4]; afl[mi][3] = al[w1 + 4];
            }
#pragma unroll
            for (int ni = 0; ni < 8; ni++) {
                int n0 = wc * 64 + ni * 8;
                int w0 = (kw + tig) * BSTRW + n0 + gr;
                int w1 = (kw + 4 + tig) * BSTRW + n0 + gr;
                bfh[ni][0] = bh[w0]; bfh[ni][1] = bh[w1];
                bfl[ni][0] = bl[w0]; bfl[ni][1] = bl[w1];
            }
#pragma unroll
            for (int mi = 0; mi < 4; mi++)
#pragma unroll
                for (int ni = 0; ni < 8; ni++) {
                    mma_bf16(acc[mi][ni], afl[mi], bfh[ni]);
                    mma_bf16(acc[mi][ni], afh[mi], bfl[ni]);
                    mma_bf16(acc[mi][ni], afh[mi], bfh[ni]);
                }
        }
        __syncthreads();
    }

#pragma unroll
    for (int mi = 0; mi < 4; mi++) {
        int m0 = row0 + wr * 64 + mi * 16;
#pragma unroll
        for (int ni = 0; ni < 8; ni++) {
            int n0 = col0 + wc * 64 + ni * 8 + 2 * tig;
            float* p0 = C + (size_t)(m0 + gr) * N + n0;
            float* p1 = C + (size_t)(m0 + 8 + gr) * N + n0;
            p0[0] = acc[mi][ni][0]; p0[1] = acc[mi][ni][1];
            p1[0] = acc[mi][ni][2]; p1[1] = acc[mi][ni][3];
        }
    }
}

// ====== FA-2 attention, all-fp16 operands: BLK_M=128, 8 warps x (m16 x n64) ======
#define HSTR 68
#define SMW_Q 0
#define SMW_K (128 * HSTR)
#define SMW_V (SMW_K + 64 * HSTR)
#define ATT_SMEM_W (SMW_V + 64 * HSTR)
#define ATT_SMEM_BYTES (ATT_SMEM_W * 4)

__global__ __launch_bounds__(256, 1) void attn_kernel() {
    extern __shared__ unsigned smu[];
    unsigned* Qw = smu + SMW_Q;
    unsigned* Kw = smu + SMW_K;
    unsigned* Vw = smu + SMW_V;
    const unsigned vbase = smem_u32(smu + SMW_V);

    const int tid = threadIdx.x;
    const int lane = tid & 31, wid = tid >> 5;
    const int gr = lane >> 2, tig = lane & 3;
    const int m0 = wid * 16;
    const int bh = blockIdx.y;
    const int b = bh >> 4, h = bh & 15;
    const int qi = (int)gridDim.x - 1 - (int)blockIdx.x;   // heavy tiles first
    const int qbase = qi * 128;

    const int len = g_len[b];
    if (qbase >= len) return;      // fully-padded q-tile: final rows are zeroed anyway

    const unsigned* Qg = g_qkvh + (size_t)b * TT * (C3/2) + (size_t)h * 64;
    const unsigned* Kg = Qg + (CC/2);
    const unsigned* Vg = Qg + 2 * (CC/2);

#pragma unroll
    for (int l = 0; l < 8; l++) {
        int chunk = l * 256 + tid;
        int row = chunk >> 4, c4 = (chunk & 15) << 2;
        asm volatile("cp.async.cg.shared.global [%0], [%1], 16;"
                     :: "r"(smem_u32(Qw + row * HSTR + c4)),
                        "l"(Qg + (size_t)(qbase + row) * (C3/2) + c4));
    }
    asm volatile("cp.async.commit_group;" ::: "memory");

    float mo0 = -INFINITY, mo1 = -INFINITY, lr0 = 0.f, lr1 = 0.f;
    float oacc[16][4];
#pragma unroll
    for (int ni = 0; ni < 16; ni++)
#pragma unroll
        for (int r = 0; r < 4; r++) oacc[ni][r] = 0.f;

    const int nkt = 2 * qi + 2;
    for (int kt = 0; kt < nkt; kt++) {
#pragma unroll
        for (int l = 0; l < 4; l++) {
            int chunk = l * 256 + tid;
            int row = chunk >> 4, c4 = (chunk & 15) << 2;
            size_t gofs = (size_t)(kt * 64 + row) * (C3/2) + c4;
            asm volatile("cp.async.cg.shared.global [%0], [%1], 16;"
                         :: "r"(smem_u32(Kw + row * HSTR + c4)), "l"(Kg + gofs));
            asm volatile("cp.async.cg.shared.global [%0], [%1], 16;"
                         :: "r"(smem_u32(Vw + row * HSTR + c4)), "l"(Vg + gofs));
        }
        asm volatile("cp.async.commit_group;" ::: "memory");
        asm volatile("cp.async.wait_group 0;" ::: "memory");
        __syncthreads();

        float sa[8][4];
#pragma unroll
        for (int ni = 0; ni < 8; ni++)
#pragma unroll
            for (int r = 0; r < 4; r++) sa[ni][r] = 0.f;

#pragma unroll
        for (int ks = 0; ks < 8; ks++) {
            const int k0 = ks * 8;
            unsigned a[4];
            a[0] = Qw[(m0 + gr)     * HSTR + k0 + tig];
            a[1] = Qw[(m0 + 8 + gr) * HSTR + k0 + tig];
            a[2] = Qw[(m0 + gr)     * HSTR + k0 + 4 + tig];
            a[3] = Qw[(m0 + 8 + gr) * HSTR + k0 + 4 + tig];
#pragma unroll
            for (int ni = 0; ni < 8; ni++) {
                unsigned bfr[2];
                bfr[0] = Kw[(ni * 8 + gr) * HSTR + k0 + tig];
                bfr[1] = Kw[(ni * 8 + gr) * HSTR + k0 + 4 + tig];
                mma_f16(sa[ni], a, bfr);
            }
        }

        if (kt >= 2 * qi) {
            int r0 = qbase + m0 + gr, r1 = r0 + 8;
#pragma unroll
            for (int ni = 0; ni < 8; ni++) {
                int c0 = kt * 64 + ni * 8 + 2 * tig;
                if (c0     > r0) sa[ni][0] = -INFINITY;
                if (c0 + 1 > r0) sa[ni][1] = -INFINITY;
                if (c0     > r1) sa[ni][2] = -INFINITY;
                if (c0 + 1 > r1) sa[ni][3] = -INFINITY;
            }
        }

        float mx0 = -INFINITY, mx1 = -INFINITY;
#pragma unroll
        for (int ni = 0; ni < 8; ni++) {
            mx0 = fmaxf(mx0, fmaxf(sa[ni][0], sa[ni][1]));
            mx1 = fmaxf(mx1, fmaxf(sa[ni][2], sa[ni][3]));
        }
        mx0 = fmaxf(mx0, __shfl_xor_sync(0xffffffffu, mx0, 1));
        mx0 = fmaxf(mx0, __shfl_xor_sync(0xffffffffu, mx0, 2));
        mx1 = fmaxf(mx1, __shfl_xor_sync(0xffffffffu, mx1, 1));
        mx1 = fmaxf(mx1, __shfl_xor_sync(0xffffffffu, mx1, 2));
        float mn0 = fmaxf(mo0, mx0), mn1 = fmaxf(mo1, mx1);
        float cf0 = (mo0 == -INFINITY) ? 0.f : __expf(mo0 - mn0);
        float cf1 = (mo1 == -INFINITY) ? 0.f : __expf(mo1 - mn1);

        unsigned ph[8][2];
        float s0 = 0.f, s1 = 0.f;
#pragma unroll
        for (int ni = 0; ni < 8; ni++) {
            float p0 = (sa[ni][0] == -INFINITY) ? 0.f : __expf(sa[ni][0] - mn0);
            float p1 = (sa[ni][1] == -INFINITY) ? 0.f : __expf(sa[ni][1] - mn0);
            float p2 = (sa[ni][2] == -INFINITY) ? 0.f : __expf(sa[ni][2] - mn1);
            float p3 = (sa[ni][3] == -INFINITY) ? 0.f : __expf(sa[ni][3] - mn1);
            s0 += p0 + p1; s1 += p2 + p3;
            ph[ni][0] = pack_h2(p0, p1);
            ph[ni][1] = pack_h2(p2, p3);
        }
        s0 += __shfl_xor_sync(0xffffffffu, s0, 1);
        s0 += __shfl_xor_sync(0xffffffffu, s0, 2);
        s1 += __shfl_xor_sync(0xffffffffu, s1, 1);
        s1 += __shfl_xor_sync(0xffffffffu, s1, 2);
        lr0 = lr0 * cf0 + s0; mo0 = mn0;
        lr1 = lr1 * cf1 + s1; mo1 = mn1;

#pragma unroll
        for (int ni = 0; ni < 16; ni++) {
            oacc[ni][0] *= cf0; oacc[ni][1] *= cf0;
            oacc[ni][2] *= cf1; oacc[ni][3] *= cf1;
        }

        unsigned pa[4][4];
#pragma unroll
        for (int j = 0; j < 4; j++) {
            pa[j][0] = ph[2 * j][0];
            pa[j][1] = ph[2 * j][1];
            pa[j][2] = ph[2 * j + 1][0];
            pa[j][3] = ph[2 * j + 1][1];
        }

#pragma unroll
        for (int jj = 0; jj < 2; jj++) {
            int vrow = 32 * jj + lane;
#pragma unroll
            for (int ni = 0; ni < 16; ni++) {
                unsigned d[4];
                ldsm_x4_trans(d, vbase + vrow * (HSTR * 4) + ni * 16);
                mma_f16(oacc[ni], pa[2 * jj],     d);
                mma_f16(oacc[ni], pa[2 * jj + 1], d + 2);
            }
        }
        __syncthreads();
    }

    // epilogue: normalize, zero padded rows, write bf16 hi/lo (A operand of out-GEMM)
    {
        int r0 = m0 + gr, r1 = m0 + 8 + gr;
        int t0 = qbase + r0, t1 = qbase + r1;
        float inv0 = (t0 < len) ? 1.0f / lr0 : 0.f;
        float inv1 = (t1 < len) ? 1.0f / lr1 : 0.f;
        size_t base0 = (((size_t)b * TT + t0) * CC + (size_t)h * DD) >> 1;
        size_t base1 = (((size_t)b * TT + t1) * CC + (size_t)h * DD) >> 1;
#pragma unroll
        for (int ni = 0; ni < 16; ni++) {
            int w = ni * 4 + tig;
            float o0 = oacc[ni][0] * inv0, o1 = oacc[ni][1] * inv0;
            float o2 = oacc[ni][2] * inv1, o3 = oacc[ni][3] * inv1;
            float l0, l1, l2, l3;
            g_ah[base0 + w] = pack_hi(o0, o1, l0, l1);
            g_al[base0 + w] = pack_bf(l0, l1);
            g_ah[base1 + w] = pack_hi(o2, o3, l2, l3);
            g_al[base1 + w] = pack_bf(l2, l3);
        }
    }
}

// ---------------- launch ----------------
extern "C" void kernel_launch(void* const* d_in, const int* in_sizes, int n_in,
                              void* d_out, int out_size) {
    const float* x    = (const float*)d_in[0];
    const void*  mask = d_in[1];
    const float* Wqkv = (const float*)d_in[2];
    const float* Wout = (const float*)d_in[3];
    float* out = (float*)d_out;

    float* qkv;    cudaGetSymbolAddress((void**)&qkv,    g_qkv);
    unsigned *xh, *xl, *ah, *al, *wqh, *wql, *woh, *wol;
    cudaGetSymbolAddress((void**)&xh,  g_xh);
    cudaGetSymbolAddress((void**)&xl,  g_xl);
    cudaGetSymbolAddress((void**)&ah,  g_ah);
    cudaGetSymbolAddress((void**)&al,  g_al);
    cudaGetSymbolAddress((void**)&wqh, g_wqkvh);
    cudaGetSymbolAddress((void**)&wql, g_wqkvl);
    cudaGetSymbolAddress((void**)&woh, g_wouth);
    cudaGetSymbolAddress((void**)&wol, g_woutl);

    // merged prep: splits + rope tables + lengths (all independent)
    prep_kernel<<<NBLK_PREP, 256>>>(x, mask, Wqkv, Wout);

    cudaFuncSetAttribute(gemm_bf16x3_kernel, cudaFuncAttributeMaxDynamicSharedMemorySize, GEMM_SMEM);

    // qkv = x @ Wqkv  (bf16x3; skip dead row-tiles, outputs unread)
    gemm_bf16x3_kernel<<<dim3(C3 / 128, BT / 128), 128, GEMM_SMEM>>>(
        xh, xl, wqh, wql, qkv, BT, C3, CC, 1);

    // RoPE q,k (scaled, fp16) + V fp16 conversion (skips dead rows)
    rope_fp16_kernel<<<ROPE_BLOCKS, 256>>>();

    // causal flash attention (skips fully-padded q-tiles)
    cudaFuncSetAttribute(attn_kernel, cudaFuncAttributeMaxDynamicSharedMemorySize, ATT_SMEM_BYTES);
    attn_kernel<<<dim3(TT / 128, BB * HH), 256, ATT_SMEM_BYTES>>>();

    // out = attn @ Wout  (bf16x3; dead row-tiles -> zeros, matching reference)
    gemm_bf16x3_kernel<<<dim3(CC / 128, BT / 128), 128, GEMM_SMEM>>>(
        ah, al, woh, wol, out, BT, CC, CC, 2);
}

// round 14
// speedup vs baseline: 1.4908x; 1.0059x over previous
#include <cuda_runtime.h>
#include <cuda_bf16.h>
#include <cuda_fp16.h>
#include <math.h>

#define BB 2
#define TT 2048
#define CC 2048
#define HH 16
#define DD 128
#define C3 (3*CC)
#define BT (BB*TT)

// ---------------- device scratch ----------------
__device__ unsigned g_qkvh[(size_t)BT * (C3/2)];       // fp16 qkv (GEMM1 fused out)
__device__ unsigned g_xh[(size_t)BT * CC / 2];
__device__ unsigned g_xl[(size_t)BT * CC / 2];
__device__ unsigned g_ah[(size_t)BT * CC / 2];
__device__ unsigned g_al[(size_t)BT * CC / 2];
__device__ unsigned g_wqkvh[(size_t)(CC/2) * C3];
__device__ unsigned g_wqkvl[(size_t)(CC/2) * C3];
__device__ unsigned g_wouth[(size_t)(CC/2) * CC];
__device__ unsigned g_woutl[(size_t)(CC/2) * CC];
__device__ float g_cos[TT * 64];
__device__ float g_sin[TT * 64];
__device__ int   g_len[BB];

// ---------------- helpers ----------------
__device__ __forceinline__ unsigned smem_u32(const void* p) {
    return (unsigned)__cvta_generic_to_shared(p);
}
__device__ __forceinline__ void mma_bf16(float* d, const unsigned* a, const unsigned* b) {
    asm volatile(
        "mma.sync.aligned.m16n8k16.row.col.f32.bf16.bf16.f32 "
        "{%0,%1,%2,%3}, {%4,%5,%6,%7}, {%8,%9}, {%0,%1,%2,%3};"
        : "+f"(d[0]), "+f"(d[1]), "+f"(d[2]), "+f"(d[3])
        : "r"(a[0]), "r"(a[1]), "r"(a[2]), "r"(a[3]), "r"(b[0]), "r"(b[1]));
}
__device__ __forceinline__ void mma_f16(float* d, const unsigned* a, const unsigned* b) {
    asm volatile(
        "mma.sync.aligned.m16n8k16.row.col.f32.f16.f16.f32 "
        "{%0,%1,%2,%3}, {%4,%5,%6,%7}, {%8,%9}, {%0,%1,%2,%3};"
        : "+f"(d[0]), "+f"(d[1]), "+f"(d[2]), "+f"(d[3])
        : "r"(a[0]), "r"(a[1]), "r"(a[2]), "r"(a[3]), "r"(b[0]), "r"(b[1]));
}
__device__ __forceinline__ void ldsm_x4_trans(unsigned* d, unsigned addr) {
    asm volatile("ldmatrix.sync.aligned.m8n8.x4.trans.shared.b16 {%0,%1,%2,%3}, [%4];"
                 : "=r"(d[0]), "=r"(d[1]), "=r"(d[2]), "=r"(d[3]) : "r"(addr));
}
__device__ __forceinline__ unsigned pack_h2(float a, float b) {
    __half2 h = __floats2half2_rn(a, b);
    return *(unsigned*)&h;
}
__device__ __forceinline__ unsigned pack_hi(float v0, float v1, float &r0, float &r1) {
    __nv_bfloat16 h0 = __float2bfloat16(v0);
    __nv_bfloat16 h1 = __float2bfloat16(v1);
    r0 = v0 - __bfloat162float(h0);
    r1 = v1 - __bfloat162float(h1);
    unsigned u0 = __bfloat16_as_ushort(h0), u1 = __bfloat16_as_ushort(h1);
    return u0 | (u1 << 16);
}
__device__ __forceinline__ unsigned pack_bf(float v0, float v1) {
    unsigned u0 = __bfloat16_as_ushort(__float2bfloat16(v0));
    unsigned u1 = __bfloat16_as_ushort(__float2bfloat16(v1));
    return u0 | (u1 << 16);
}

// ================= merged prep kernel: splits + rope tables + lengths =============
#define NBLK_A 16384
#define NBLK_B 24576
#define NBLK_C 8192
#define NBLK_D 512
#define NBLK_E 2
#define NBLK_PREP (NBLK_A + NBLK_B + NBLK_C + NBLK_D + NBLK_E)

__device__ __forceinline__ void split_b_elem(const float* __restrict__ W,
                                             unsigned* dh, unsigned* dl,
                                             int N, size_t idx) {
    int n = (int)(idx % N);
    int k2 = (int)(idx / N);
    float v0 = W[(size_t)(2 * k2) * N + n];
    float v1 = W[(size_t)(2 * k2 + 1) * N + n];
    float l0, l1;
    dh[idx] = pack_hi(v0, v1, l0, l1);
    dl[idx] = pack_bf(l0, l1);
}

__global__ void prep_kernel(const float* __restrict__ x, const void* __restrict__ mask,
                            const float* __restrict__ Wqkv, const float* __restrict__ Wout) {
    __shared__ int ssum[256];
    unsigned bi = blockIdx.x;
    int tid = threadIdx.x;
    if (bi < NBLK_A) {
        size_t w = (size_t)bi * 256 + tid;
        float2 v = *(const float2*)&x[w * 2];
        float l0, l1;
        g_xh[w] = pack_hi(v.x, v.y, l0, l1);
        g_xl[w] = pack_bf(l0, l1);
    } else if (bi < NBLK_A + NBLK_B) {
        size_t idx = (size_t)(bi - NBLK_A) * 256 + tid;
        split_b_elem(Wqkv, g_wqkvh, g_wqkvl, C3, idx);
    } else if (bi < NBLK_A + NBLK_B + NBLK_C) {
        size_t idx = (size_t)(bi - NBLK_A - NBLK_B) * 256 + tid;
        split_b_elem(Wout, g_wouth, g_woutl, CC, idx);
    } else if (bi < NBLK_A + NBLK_B + NBLK_C + NBLK_D) {
        int idx = (int)(bi - NBLK_A - NBLK_B - NBLK_C) * 256 + tid;
        int t = idx >> 6, i = idx & 63;
        float invf = (float)(1.0 / pow(10000.0, (double)i / 64.0));
        float ang = (float)t * invf;
        double a = (double)ang;
        g_cos[idx] = (float)cos(a);
        g_sin[idx] = (float)sin(a);
    } else {
        int b = (int)(bi - NBLK_A - NBLK_B - NBLK_C - NBLK_D);
        unsigned int w0 = *(const unsigned int*)mask;
        int cnt = 0;
        if (w0 == 0x01010101u) {
            const unsigned char* m = (const unsigned char*)mask + (size_t)b * TT;
            for (int i = tid; i < TT; i += 256) cnt += (m[i] != 0);
        } else if (w0 == 0x3F800000u) {
            const float* m = (const float*)mask + (size_t)b * TT;
            for (int i = tid; i < TT; i += 256) cnt += (m[i] != 0.0f);
        } else {
            const int* m = (const int*)mask + (size_t)b * TT;
            for (int i = tid; i < TT; i += 256) cnt += (m[i] != 0);
        }
        ssum[tid] = cnt;
        __syncthreads();
        for (int s = 128; s > 0; s >>= 1) {
            if (tid < s) ssum[tid] += ssum[tid + s];
            __syncthreads();
        }
        if (tid == 0) g_len[b] = ssum[0];
    }
}

// ================= bf16x3 tensor-core GEMM ==============
// mode 1: fused RoPE+fp16 epilogue -> g_qkvh (GEMM1); skip dead row-tiles silently.
// mode 2: fp32 C out (GEMM2); dead row-tiles -> write zeros.
#define KCB 32
#define ASTRW 20
#define BSTRW 136
#define ATILEW (128 * ASTRW)
#define BTILEW (16 * BSTRW)
#define GEMM_SMEM ((4 * ATILEW + 4 * BTILEW) * 4)   // 75776 B (also fits 128x132 f32 staging)
#define STGSTR 132

__device__ __forceinline__ void gemm_load_chunk_bf(
    unsigned* Ah, unsigned* Al, unsigned* Bh, unsigned* Bl,
    const unsigned* __restrict__ Agh, const unsigned* __restrict__ Agl,
    const unsigned* __restrict__ Bgh, const unsigned* __restrict__ Bgl,
    int row0, int col0, int kc, int K, int N, int tid)
{
    const int Kw = K >> 1;
#pragma unroll
    for (int i = 0; i < 4; i++) {
        int c = i * 128 + tid;
        int row = c >> 2, segw = (c & 3) << 2;
        size_t gsrc = (size_t)(row0 + row) * Kw + (kc >> 1) + segw;
        int dstw = row * ASTRW + segw;
        asm volatile("cp.async.cg.shared.global [%0], [%1], 16;"
                     :: "r"(smem_u32(Ah + dstw)), "l"(Agh + gsrc));
        asm volatile("cp.async.cg.shared.global [%0], [%1], 16;"
                     :: "r"(smem_u32(Al + dstw)), "l"(Agl + gsrc));
    }
#pragma unroll
    for (int i = 0; i < 4; i++) {
        int c = i * 128 + tid;
        int krow = c >> 5, segw = (c & 31) << 2;
        size_t gsrc = (size_t)((kc >> 1) + krow) * N + col0 + segw;
        int dstw = krow * BSTRW + segw;
        asm volatile("cp.async.cg.shared.global [%0], [%1], 16;"
                     :: "r"(smem_u32(Bh + dstw)), "l"(Bgh + gsrc));
        asm volatile("cp.async.cg.shared.global [%0], [%1], 16;"
                     :: "r"(smem_u32(Bl + dstw)), "l"(Bgl + gsrc));
    }
    asm volatile("cp.async.commit_group;");
}

__global__ __launch_bounds__(128, 2) void gemm_bf16x3_kernel(
    const unsigned* __restrict__ Agh, const unsigned* __restrict__ Agl,
    const unsigned* __restrict__ Bgh, const unsigned* __restrict__ Bgl,
    float* __restrict__ C, int M, int N, int K, int mode)
{
    extern __shared__ unsigned smw[];
    unsigned* Ah = smw;
    unsigned* Al = smw + 2 * ATILEW;
    unsigned* Bh = smw + 4 * ATILEW;
    unsigned* Bl = smw + 4 * ATILEW + 2 * BTILEW;

    const int tid  = threadIdx.x;
    const int lane = tid & 31, warp = tid >> 5;
    const int wr = warp >> 1, wc = warp & 1;
    const int gr = lane >> 2, tig = lane & 3;
    const int row0 = blockIdx.y * 128, col0 = blockIdx.x * 128;

    const int bb = row0 / TT;
    const int len = g_len[bb];
    if ((row0 % TT) >= len) {
        if (mode == 2) {
#pragma unroll
            for (int mi = 0; mi < 4; mi++) {
                int m0 = row0 + wr * 64 + mi * 16;
#pragma unroll
                for (int ni = 0; ni < 8; ni++) {
                    int n0 = col0 + wc * 64 + ni * 8 + 2 * tig;
                    float* p0 = C + (size_t)(m0 + gr) * N + n0;
                    float* p1 = C + (size_t)(m0 + 8 + gr) * N + n0;
                    p0[0] = 0.f; p0[1] = 0.f;
                    p1[0] = 0.f; p1[1] = 0.f;
                }
            }
        }
        return;
    }

    float acc[4][8][4];
#pragma unroll
    for (int mi = 0; mi < 4; mi++)
#pragma unroll
        for (int ni = 0; ni < 8; ni++)
#pragma unroll
            for (int r = 0; r < 4; r++) acc[mi][ni][r] = 0.f;

    const int nc = K / KCB;
    gemm_load_chunk_bf(Ah, Al, Bh, Bl, Agh, Agl, Bgh, Bgl, row0, col0, 0, K, N, tid);

    for (int c = 0; c < nc; c++) {
        if (c + 1 < nc) {
            int nb = (c + 1) & 1;
            gemm_load_chunk_bf(Ah + nb * ATILEW, Al + nb * ATILEW,
                               Bh + nb * BTILEW, Bl + nb * BTILEW,
                               Agh, Agl, Bgh, Bgl, row0, col0, (c + 1) * KCB, K, N, tid);
            asm volatile("cp.async.wait_group 1;");
        } else {
            asm volatile("cp.async.wait_group 0;");
        }
        __syncthreads();

        const unsigned* ah = Ah + (c & 1) * ATILEW;
        const unsigned* al = Al + (c & 1) * ATILEW;
        const unsigned* bh = Bh + (c & 1) * BTILEW;
        const unsigned* bl = Bl + (c & 1) * BTILEW;

#pragma unroll
        for (int s = 0; s < 2; s++) {
            const int kw = s * 8;
            unsigned afh[4][4], afl[4][4], bfh[8][2], bfl[8][2];
#pragma unroll
            for (int mi = 0; mi < 4; mi++) {
                int m0 = wr * 64 + mi * 16;
                int w0 = (m0 + gr) * ASTRW + kw + tig;
                int w1 = (m0 + 8 + gr) * ASTRW + kw + tig;
                afh[mi][0] = ah[w0];     afh[mi][1] = ah[w1];
                afh[mi][2] = ah[w0 + 4]; afh[mi][3] = ah[w1 + 4];
                afl[mi][0] = al[w0];     afl[mi][1] = al[w1];
                afl[mi][2] = al[w0 + 4]; afl[mi][3] = al[w1 + 4];
            }
#pragma unroll
            for (int ni = 0; ni < 8; ni++) {
                int n0 = wc * 64 + ni * 8;
                int w0 = (kw + tig) * BSTRW + n0 + gr;
                int w1 = (kw + 4 + tig) * BSTRW + n0 + gr;
                bfh[ni][0] = bh[w0]; bfh[ni][1] = bh[w1];
                bfl[ni][0] = bl[w0]; bfl[ni][1] = bl[w1];
            }
#pragma unroll
            for (int mi = 0; mi < 4; mi++)
#pragma unroll
                for (int ni = 0; ni < 8; ni++) {
                    mma_bf16(acc[mi][ni], afl[mi], bfh[ni]);
                    mma_bf16(acc[mi][ni], afh[mi], bfl[ni]);
                    mma_bf16(acc[mi][ni], afh[mi], bfh[ni]);
                }
        }
        __syncthreads();
    }

    if (mode == 2) {
        // plain fp32 epilogue
#pragma unroll
        for (int mi = 0; mi < 4; mi++) {
            int m0 = row0 + wr * 64 + mi * 16;
#pragma unroll
            for (int ni = 0; ni < 8; ni++) {
                int n0 = col0 + wc * 64 + ni * 8 + 2 * tig;
                float* p0 = C + (size_t)(m0 + gr) * N + n0;
                float* p1 = C + (size_t)(m0 + 8 + gr) * N + n0;
                p0[0] = acc[mi][ni][0]; p0[1] = acc[mi][ni][1];
                p1[0] = acc[mi][ni][2]; p1[1] = acc[mi][ni][3];
            }
        }
        return;
    }

    // ----- mode 1: fused RoPE (+1/sqrt(d) for Q) + fp16 pack -> g_qkvh -----
    // stage fp32 tile in smem (mainloop buffers are dead now)
    float* stg = (float*)smw;
#pragma unroll
    for (int mi = 0; mi < 4; mi++) {
        int mr = wr * 64 + mi * 16;
#pragma unroll
        for (int ni = 0; ni < 8; ni++) {
            int n0 = wc * 64 + ni * 8 + 2 * tig;
            *(float2*)&stg[(mr + gr) * STGSTR + n0] =
                make_float2(acc[mi][ni][0], acc[mi][ni][1]);
            *(float2*)&stg[(mr + 8 + gr) * STGSTR + n0] =
                make_float2(acc[mi][ni][2], acc[mi][ni][3]);
        }
    }
    __syncthreads();

    const int sec = col0 / CC;             // 0=Q, 1=K, 2=V (tile never straddles: CC%128==0)
    const int h = (col0 % CC) / DD;        // head (tile exactly covers one head)
    const int jw = tid & 63;               // output word within row
    const int r2 = tid >> 6;               // row parity (2 rows per iteration)
    const float scale = 0.08838834764831845f;

    for (int it = 0; it < 64; it++) {
        int r = r2 + it * 2;
        int t = (row0 % TT) + r;
        if (t >= len) continue;            // dead row: never read downstream
        size_t whead = ((size_t)(bb * TT + t)) * (C3/2) + (size_t)sec * (CC/2) + (size_t)h * 64;
        float out0, out1;
        if (sec == 2) {
            float2 v = *(float2*)&stg[r * STGSTR + 2 * jw];
            out0 = v.x; out1 = v.y;
        } else if (jw < 32) {
            int cidx = 2 * jw;             // cols < 64
            float2 x1 = *(float2*)&stg[r * STGSTR + cidx];
            float2 x2 = *(float2*)&stg[r * STGSTR + cidx + 64];
            float c0 = g_cos[t * 64 + cidx],     s0 = g_sin[t * 64 + cidx];
            float c1 = g_cos[t * 64 + cidx + 1], s1 = g_sin[t * 64 + cidx + 1];
            out0 = x1.x * c0 - x2.x * s0;
            out1 = x1.y * c1 - x2.y * s1;
            if (sec == 0) { out0 *= scale; out1 *= scale; }
        } else {
            int cidx = 2 * jw;             // cols >= 64
            int cc = cidx - 64;
            float2 x2 = *(float2*)&stg[r * STGSTR + cidx];
            float2 x1 = *(float2*)&stg[r * STGSTR + cc];
            float c0 = g_cos[t * 64 + cc],     s0 = g_sin[t * 64 + cc];
            float c1 = g_cos[t * 64 + cc + 1], s1 = g_sin[t * 64 + cc + 1];
            out0 = x2.x * c0 + x1.x * s0;
            out1 = x2.y * c1 + x1.y * s1;
            if (sec == 0) { out0 *= scale; out1 *= scale; }
        }
        g_qkvh[whead + jw] = pack_h2(out0, out1);
    }
}

// ====== FA-2 attention, all-fp16 operands: BLK_M=128, 8 warps x (m16 x n64) ======
#define HSTR 68
#define SMW_Q 0
#define SMW_K (128 * HSTR)
#define SMW_V (SMW_K + 64 * HSTR)
#define ATT_SMEM_W (SMW_V + 64 * HSTR)
#define ATT_SMEM_BYTES (ATT_SMEM_W * 4)

__global__ __launch_bounds__(256, 1) void attn_kernel() {
    extern __shared__ unsigned smu[];
    unsigned* Qw = smu + SMW_Q;
    unsigned* Kw = smu + SMW_K;
    unsigned* Vw = smu + SMW_V;
    const unsigned vbase = smem_u32(smu + SMW_V);

    const int tid = threadIdx.x;
    const int lane = tid & 31, wid = tid >> 5;
    const int gr = lane >> 2, tig = lane & 3;
    const int m0 = wid * 16;
    const int bh = blockIdx.y;
    const int b = bh >> 4, h = bh & 15;
    const int qi = (int)gridDim.x - 1 - (int)blockIdx.x;   // heavy tiles first
    const int qbase = qi * 128;

    const int len = g_len[b];
    if (qbase >= len) return;

    const unsigned* Qg = g_qkvh + (size_t)b * TT * (C3/2) + (size_t)h * 64;
    const unsigned* Kg = Qg + (CC/2);
    const unsigned* Vg = Qg + 2 * (CC/2);

#pragma unroll
    for (int l = 0; l < 8; l++) {
        int chunk = l * 256 + tid;
        int row = chunk >> 4, c4 = (chunk & 15) << 2;
        asm volatile("cp.async.cg.shared.global [%0], [%1], 16;"
                     :: "r"(smem_u32(Qw + row * HSTR + c4)),
                        "l"(Qg + (size_t)(qbase + row) * (C3/2) + c4));
    }
    asm volatile("cp.async.commit_group;" ::: "memory");

    float mo0 = -INFINITY, mo1 = -INFINITY, lr0 = 0.f, lr1 = 0.f;
    float oacc[16][4];
#pragma unroll
    for (int ni = 0; ni < 16; ni++)
#pragma unroll
        for (int r = 0; r < 4; r++) oacc[ni][r] = 0.f;

    const int nkt = 2 * qi + 2;
    for (int kt = 0; kt < nkt; kt++) {
#pragma unroll
        for (int l = 0; l < 4; l++) {
            int chunk = l * 256 + tid;
            int row = chunk >> 4, c4 = (chunk & 15) << 2;
            size_t gofs = (size_t)(kt * 64 + row) * (C3/2) + c4;
            asm volatile("cp.async.cg.shared.global [%0], [%1], 16;"
                         :: "r"(smem_u32(Kw + row * HSTR + c4)), "l"(Kg + gofs));
            asm volatile("cp.async.cg.shared.global [%0], [%1], 16;"
                         :: "r"(smem_u32(Vw + row * HSTR + c4)), "l"(Vg + gofs));
        }
        asm volatile("cp.async.commit_group;" ::: "memory");
        asm volatile("cp.async.wait_group 0;" ::: "memory");
        __syncthreads();

        float sa[8][4];
#pragma unroll
        for (int ni = 0; ni < 8; ni++)
#pragma unroll
            for (int r = 0; r < 4; r++) sa[ni][r] = 0.f;

#pragma unroll
        for (int ks = 0; ks < 8; ks++) {
            const int k0 = ks * 8;
            unsigned a[4];
            a[0] = Qw[(m0 + gr)     * HSTR + k0 + tig];
            a[1] = Qw[(m0 + 8 + gr) * HSTR + k0 + tig];
            a[2] = Qw[(m0 + gr)     * HSTR + k0 + 4 + tig];
            a[3] = Qw[(m0 + 8 + gr) * HSTR + k0 + 4 + tig];
#pragma unroll
            for (int ni = 0; ni < 8; ni++) {
                unsigned bfr[2];
                bfr[0] = Kw[(ni * 8 + gr) * HSTR + k0 + tig];
                bfr[1] = Kw[(ni * 8 + gr) * HSTR + k0 + 4 + tig];
                mma_f16(sa[ni], a, bfr);
            }
        }

        if (kt >= 2 * qi) {
            int r0 = qbase + m0 + gr, r1 = r0 + 8;
#pragma unroll
            for (int ni = 0; ni < 8; ni++) {
                int c0 = kt * 64 + ni * 8 + 2 * tig;
                if (c0     > r0) sa[ni][0] = -INFINITY;
                if (c0 + 1 > r0) sa[ni][1] = -INFINITY;
                if (c0     > r1) sa[ni][2] = -INFINITY;
                if (c0 + 1 > r1) sa[ni][3] = -INFINITY;
            }
        }

        float mx0 = -INFINITY, mx1 = -INFINITY;
#pragma unroll
        for (int ni = 0; ni < 8; ni++) {
            mx0 = fmaxf(mx0, fmaxf(sa[ni][0], sa[ni][1]));
            mx1 = fmaxf(mx1, fmaxf(sa[ni][2], sa[ni][3]));
        }
        mx0 = fmaxf(mx0, __shfl_xor_sync(0xffffffffu, mx0, 1));
        mx0 = fmaxf(mx0, __shfl_xor_sync(0xffffffffu, mx0, 2));
        mx1 = fmaxf(mx1, __shfl_xor_sync(0xffffffffu, mx1, 1));
        mx1 = fmaxf(mx1, __shfl_xor_sync(0xffffffffu, mx1, 2));
        float mn0 = fmaxf(mo0, mx0), mn1 = fmaxf(mo1, mx1);
        float cf0 = (mo0 == -INFINITY) ? 0.f : __expf(mo0 - mn0);
        float cf1 = (mo1 == -INFINITY) ? 0.f : __expf(mo1 - mn1);

        unsigned ph[8][2];
        float s0 = 0.f, s1 = 0.f;
#pragma unroll
        for (int ni = 0; ni < 8; ni++) {
            float p0 = (sa[ni][0] == -INFINITY) ? 0.f : __expf(sa[ni][0] - mn0);
            float p1 = (sa[ni][1] == -INFINITY) ? 0.f : __expf(sa[ni][1] - mn0);
            float p2 = (sa[ni][2] == -INFINITY) ? 0.f : __expf(sa[ni][2] - mn1);
            float p3 = (sa[ni][3] == -INFINITY) ? 0.f : __expf(sa[ni][3] - mn1);
            s0 += p0 + p1; s1 += p2 + p3;
            ph[ni][0] = pack_h2(p0, p1);
            ph[ni][1] = pack_h2(p2, p3);
        }
        s0 += __shfl_xor_sync(0xffffffffu, s0, 1);
        s0 += __shfl_xor_sync(0xffffffffu, s0, 2);
        s1 += __shfl_xor_sync(0xffffffffu, s1, 1);
        s1 += __shfl_xor_sync(0xffffffffu, s1, 2);
        lr0 = lr0 * cf0 + s0; mo0 = mn0;
        lr1 = lr1 * cf1 + s1; mo1 = mn1;

#pragma unroll
        for (int ni = 0; ni < 16; ni++) {
            oacc[ni][0] *= cf0; oacc[ni][1] *= cf0;
            oacc[ni][2] *= cf1; oacc[ni][3] *= cf1;
        }

        unsigned pa[4][4];
#pragma unroll
        for (int j = 0; j < 4; j++) {
            pa[j][0] = ph[2 * j][0];
            pa[j][1] = ph[2 * j][1];
            pa[j][2] = ph[2 * j + 1][0];
            pa[j][3] = ph[2 * j + 1][1];
        }

#pragma unroll
        for (int jj = 0; jj < 2; jj++) {
            int vrow = 32 * jj + lane;
#pragma unroll
            for (int ni = 0; ni < 16; ni++) {
                unsigned d[4];
                ldsm_x4_trans(d, vbase + vrow * (HSTR * 4) + ni * 16);
                mma_f16(oacc[ni], pa[2 * jj],     d);
                mma_f16(oacc[ni], pa[2 * jj + 1], d + 2);
            }
        }
        __syncthreads();
    }

    // epilogue: normalize, zero padded rows, write bf16 hi/lo (A operand of out-GEMM)
    {
        int r0 = m0 + gr, r1 = m0 + 8 + gr;
        int t0 = qbase + r0, t1 = qbase + r1;
        float inv0 = (t0 < len) ? 1.0f / lr0 : 0.f;
        float inv1 = (t1 < len) ? 1.0f / lr1 : 0.f;
        size_t base0 = (((size_t)b * TT + t0) * CC + (size_t)h * DD) >> 1;
        size_t base1 = (((size_t)b * TT + t1) * CC + (size_t)h * DD) >> 1;
#pragma unroll
        for (int ni = 0; ni < 16; ni++) {
            int w = ni * 4 + tig;
            float o0 = oacc[ni][0] * inv0, o1 = oacc[ni][1] * inv0;
            float o2 = oacc[ni][2] * inv1, o3 = oacc[ni][3] * inv1;
            float l0, l1, l2, l3;
            g_ah[base0 + w] = pack_hi(o0, o1, l0, l1);
            g_al[base0 + w] = pack_bf(l0, l1);
            g_ah[base1 + w] = pack_hi(o2, o3, l2, l3);
            g_al[base1 + w] = pack_bf(l2, l3);
        }
    }
}

// ---------------- launch ----------------
extern "C" void kernel_launch(void* const* d_in, const int* in_sizes, int n_in,
                              void* d_out, int out_size) {
    const float* x    = (const float*)d_in[0];
    const void*  mask = d_in[1];
    const float* Wqkv = (const float*)d_in[2];
    const float* Wout = (const float*)d_in[3];
    float* out = (float*)d_out;

    unsigned *xh, *xl, *ah, *al, *wqh, *wql, *woh, *wol;
    cudaGetSymbolAddress((void**)&xh,  g_xh);
    cudaGetSymbolAddress((void**)&xl,  g_xl);
    cudaGetSymbolAddress((void**)&ah,  g_ah);
    cudaGetSymbolAddress((void**)&al,  g_al);
    cudaGetSymbolAddress((void**)&wqh, g_wqkvh);
    cudaGetSymbolAddress((void**)&wql, g_wqkvl);
    cudaGetSymbolAddress((void**)&woh, g_wouth);
    cudaGetSymbolAddress((void**)&wol, g_woutl);

    // merged prep: splits + rope tables + lengths (all independent)
    prep_kernel<<<NBLK_PREP, 256>>>(x, mask, Wqkv, Wout);

    cudaFuncSetAttribute(gemm_bf16x3_kernel, cudaFuncAttributeMaxDynamicSharedMemorySize, GEMM_SMEM);

    // qkv(fp16, rotated, scaled) = RoPE(x @ Wqkv)  — fused epilogue, dead tiles skipped
    gemm_bf16x3_kernel<<<dim3(C3 / 128, BT / 128), 128, GEMM_SMEM>>>(
        xh, xl, wqh, wql, nullptr, BT, C3, CC, 1);

    // causal flash attention (all-fp16, warp-local softmax, dead q-tiles skipped)
    cudaFuncSetAttribute(attn_kernel, cudaFuncAttributeMaxDynamicSharedMemorySize, ATT_SMEM_BYTES);
    attn_kernel<<<dim3(TT / 128, BB * HH), 256, ATT_SMEM_BYTES>>>();

    // out = attn @ Wout  (bf16x3; dead row-tiles -> zeros, matching reference)
    gemm_bf16x3_kernel<<<dim3(CC / 128, BT / 128), 128, GEMM_SMEM>>>(
        ah, al, woh, wol, out, BT, CC, CC, 2);
}

// round 15
// speedup vs baseline: 1.5021x; 1.0076x over previous
#include <cuda_runtime.h>
#include <cuda_bf16.h>
#include <cuda_fp16.h>
#include <math.h>

#define BB 2
#define TT 2048
#define CC 2048
#define HH 16
#define DD 128
#define C3 (3*CC)
#define BT (BB*TT)

// ---------------- device scratch ----------------
__device__ unsigned g_qkvh[(size_t)BT * (C3/2)];       // fp16 qkv (GEMM1 fused out)
__device__ unsigned g_xh[(size_t)BT * CC / 2];
__device__ unsigned g_xl[(size_t)BT * CC / 2];
__device__ unsigned g_ah[(size_t)BT * CC / 2];
__device__ unsigned g_al[(size_t)BT * CC / 2];
__device__ unsigned g_wqkvh[(size_t)(CC/2) * C3];
__device__ unsigned g_wqkvl[(size_t)(CC/2) * C3];
__device__ unsigned g_wouth[(size_t)(CC/2) * CC];
__device__ unsigned g_woutl[(size_t)(CC/2) * CC];
__device__ float g_cos[TT * 64];
__device__ float g_sin[TT * 64];
__device__ int   g_len[BB];

// ---------------- helpers ----------------
__device__ __forceinline__ unsigned smem_u32(const void* p) {
    return (unsigned)__cvta_generic_to_shared(p);
}
__device__ __forceinline__ void mma_bf16(float* d, const unsigned* a, const unsigned* b) {
    asm volatile(
        "mma.sync.aligned.m16n8k16.row.col.f32.bf16.bf16.f32 "
        "{%0,%1,%2,%3}, {%4,%5,%6,%7}, {%8,%9}, {%0,%1,%2,%3};"
        : "+f"(d[0]), "+f"(d[1]), "+f"(d[2]), "+f"(d[3])
        : "r"(a[0]), "r"(a[1]), "r"(a[2]), "r"(a[3]), "r"(b[0]), "r"(b[1]));
}
__device__ __forceinline__ void mma_f16(float* d, const unsigned* a, const unsigned* b) {
    asm volatile(
        "mma.sync.aligned.m16n8k16.row.col.f32.f16.f16.f32 "
        "{%0,%1,%2,%3}, {%4,%5,%6,%7}, {%8,%9}, {%0,%1,%2,%3};"
        : "+f"(d[0]), "+f"(d[1]), "+f"(d[2]), "+f"(d[3])
        : "r"(a[0]), "r"(a[1]), "r"(a[2]), "r"(a[3]), "r"(b[0]), "r"(b[1]));
}
__device__ __forceinline__ void ldsm_x4_trans(unsigned* d, unsigned addr) {
    asm volatile("ldmatrix.sync.aligned.m8n8.x4.trans.shared.b16 {%0,%1,%2,%3}, [%4];"
                 : "=r"(d[0]), "=r"(d[1]), "=r"(d[2]), "=r"(d[3]) : "r"(addr));
}
__device__ __forceinline__ unsigned pack_h2(float a, float b) {
    __half2 h = __floats2half2_rn(a, b);
    return *(unsigned*)&h;
}
__device__ __forceinline__ unsigned pack_hi(float v0, float v1, float &r0, float &r1) {
    __nv_bfloat16 h0 = __float2bfloat16(v0);
    __nv_bfloat16 h1 = __float2bfloat16(v1);
    r0 = v0 - __bfloat162float(h0);
    r1 = v1 - __bfloat162float(h1);
    unsigned u0 = __bfloat16_as_ushort(h0), u1 = __bfloat16_as_ushort(h1);
    return u0 | (u1 << 16);
}
__device__ __forceinline__ unsigned pack_bf(float v0, float v1) {
    unsigned u0 = __bfloat16_as_ushort(__float2bfloat16(v0));
    unsigned u1 = __bfloat16_as_ushort(__float2bfloat16(v1));
    return u0 | (u1 << 16);
}

// ================= merged prep kernel: splits + rope tables + lengths =============
#define NBLK_A 16384
#define NBLK_B 24576
#define NBLK_C 8192
#define NBLK_D 512
#define NBLK_E 2
#define NBLK_PREP (NBLK_A + NBLK_B + NBLK_C + NBLK_D + NBLK_E)

__device__ __forceinline__ void split_b_elem(const float* __restrict__ W,
                                             unsigned* dh, unsigned* dl,
                                             int N, size_t idx) {
    int n = (int)(idx % N);
    int k2 = (int)(idx / N);
    float v0 = W[(size_t)(2 * k2) * N + n];
    float v1 = W[(size_t)(2 * k2 + 1) * N + n];
    float l0, l1;
    dh[idx] = pack_hi(v0, v1, l0, l1);
    dl[idx] = pack_bf(l0, l1);
}

__global__ void prep_kernel(const float* __restrict__ x, const void* __restrict__ mask,
                            const float* __restrict__ Wqkv, const float* __restrict__ Wout) {
    __shared__ int ssum[256];
    unsigned bi = blockIdx.x;
    int tid = threadIdx.x;
    if (bi < NBLK_A) {
        size_t w = (size_t)bi * 256 + tid;
        float2 v = *(const float2*)&x[w * 2];
        float l0, l1;
        g_xh[w] = pack_hi(v.x, v.y, l0, l1);
        g_xl[w] = pack_bf(l0, l1);
    } else if (bi < NBLK_A + NBLK_B) {
        size_t idx = (size_t)(bi - NBLK_A) * 256 + tid;
        split_b_elem(Wqkv, g_wqkvh, g_wqkvl, C3, idx);
    } else if (bi < NBLK_A + NBLK_B + NBLK_C) {
        size_t idx = (size_t)(bi - NBLK_A - NBLK_B) * 256 + tid;
        split_b_elem(Wout, g_wouth, g_woutl, CC, idx);
    } else if (bi < NBLK_A + NBLK_B + NBLK_C + NBLK_D) {
        int idx = (int)(bi - NBLK_A - NBLK_B - NBLK_C) * 256 + tid;
        int t = idx >> 6, i = idx & 63;
        float invf = (float)(1.0 / pow(10000.0, (double)i / 64.0));
        float ang = (float)t * invf;
        double a = (double)ang;
        g_cos[idx] = (float)cos(a);
        g_sin[idx] = (float)sin(a);
    } else {
        int b = (int)(bi - NBLK_A - NBLK_B - NBLK_C - NBLK_D);
        unsigned int w0 = *(const unsigned int*)mask;
        int cnt = 0;
        if (w0 == 0x01010101u) {
            const unsigned char* m = (const unsigned char*)mask + (size_t)b * TT;
            for (int i = tid; i < TT; i += 256) cnt += (m[i] != 0);
        } else if (w0 == 0x3F800000u) {
            const float* m = (const float*)mask + (size_t)b * TT;
            for (int i = tid; i < TT; i += 256) cnt += (m[i] != 0.0f);
        } else {
            const int* m = (const int*)mask + (size_t)b * TT;
            for (int i = tid; i < TT; i += 256) cnt += (m[i] != 0);
        }
        ssum[tid] = cnt;
        __syncthreads();
        for (int s = 128; s > 0; s >>= 1) {
            if (tid < s) ssum[tid] += ssum[tid + s];
            __syncthreads();
        }
        if (tid == 0) g_len[b] = ssum[0];
    }
}

// ================= bf16x3 GEMM mainloop (shared by both GEMM kernels) =============
#define KCB 32
#define ASTRW 20
#define BSTRW 136
#define ATILEW (128 * ASTRW)
#define BTILEW (16 * BSTRW)
#define GEMM_SMEM ((4 * ATILEW + 4 * BTILEW) * 4)   // 75776 B
#define STGSTR 132

__device__ __forceinline__ void gemm_load_chunk_bf(
    unsigned* Ah, unsigned* Al, unsigned* Bh, unsigned* Bl,
    const unsigned* __restrict__ Agh, const unsigned* __restrict__ Agl,
    const unsigned* __restrict__ Bgh, const unsigned* __restrict__ Bgl,
    int row0, int col0, int kc, int K, int N, int tid)
{
    const int Kw = K >> 1;
#pragma unroll
    for (int i = 0; i < 4; i++) {
        int c = i * 128 + tid;
        int row = c >> 2, segw = (c & 3) << 2;
        size_t gsrc = (size_t)(row0 + row) * Kw + (kc >> 1) + segw;
        int dstw = row * ASTRW + segw;
        asm volatile("cp.async.cg.shared.global [%0], [%1], 16;"
                     :: "r"(smem_u32(Ah + dstw)), "l"(Agh + gsrc));
        asm volatile("cp.async.cg.shared.global [%0], [%1], 16;"
                     :: "r"(smem_u32(Al + dstw)), "l"(Agl + gsrc));
    }
#pragma unroll
    for (int i = 0; i < 4; i++) {
        int c = i * 128 + tid;
        int krow = c >> 5, segw = (c & 31) << 2;
        size_t gsrc = (size_t)((kc >> 1) + krow) * N + col0 + segw;
        int dstw = krow * BSTRW + segw;
        asm volatile("cp.async.cg.shared.global [%0], [%1], 16;"
                     :: "r"(smem_u32(Bh + dstw)), "l"(Bgh + gsrc));
        asm volatile("cp.async.cg.shared.global [%0], [%1], 16;"
                     :: "r"(smem_u32(Bl + dstw)), "l"(Bgl + gsrc));
    }
    asm volatile("cp.async.commit_group;");
}

__device__ __forceinline__ void gemm_mainloop(
    unsigned* smw, float acc[4][8][4],
    const unsigned* __restrict__ Agh, const unsigned* __restrict__ Agl,
    const unsigned* __restrict__ Bgh, const unsigned* __restrict__ Bgl,
    int row0, int col0, int K, int N,
    int tid, int wr, int wc, int gr, int tig)
{
    unsigned* Ah = smw;
    unsigned* Al = smw + 2 * ATILEW;
    unsigned* Bh = smw + 4 * ATILEW;
    unsigned* Bl = smw + 4 * ATILEW + 2 * BTILEW;

#pragma unroll
    for (int mi = 0; mi < 4; mi++)
#pragma unroll
        for (int ni = 0; ni < 8; ni++)
#pragma unroll
            for (int r = 0; r < 4; r++) acc[mi][ni][r] = 0.f;

    const int nc = K / KCB;
    gemm_load_chunk_bf(Ah, Al, Bh, Bl, Agh, Agl, Bgh, Bgl, row0, col0, 0, K, N, tid);

    for (int c = 0; c < nc; c++) {
        if (c + 1 < nc) {
            int nb = (c + 1) & 1;
            gemm_load_chunk_bf(Ah + nb * ATILEW, Al + nb * ATILEW,
                               Bh + nb * BTILEW, Bl + nb * BTILEW,
                               Agh, Agl, Bgh, Bgl, row0, col0, (c + 1) * KCB, K, N, tid);
            asm volatile("cp.async.wait_group 1;");
        } else {
            asm volatile("cp.async.wait_group 0;");
        }
        __syncthreads();

        const unsigned* ah = Ah + (c & 1) * ATILEW;
        const unsigned* al = Al + (c & 1) * ATILEW;
        const unsigned* bh = Bh + (c & 1) * BTILEW;
        const unsigned* bl = Bl + (c & 1) * BTILEW;

#pragma unroll
        for (int s = 0; s < 2; s++) {
            const int kw = s * 8;
            unsigned afh[4][4], afl[4][4], bfh[8][2], bfl[8][2];
#pragma unroll
            for (int mi = 0; mi < 4; mi++) {
                int m0 = wr * 64 + mi * 16;
                int w0 = (m0 + gr) * ASTRW + kw + tig;
                int w1 = (m0 + 8 + gr) * ASTRW + kw + tig;
                afh[mi][0] = ah[w0];     afh[mi][1] = ah[w1];
                afh[mi][2] = ah[w0 + 4]; afh[mi][3] = ah[w1 + 4];
                afl[mi][0] = al[w0];     afl[mi][1] = al[w1];
                afl[mi][2] = al[w0 + 4]; afl[mi][3] = al[w1 + 4];
            }
#pragma unroll
            for (int ni = 0; ni < 8; ni++) {
                int n0 = wc * 64 + ni * 8;
                int w0 = (kw + tig) * BSTRW + n0 + gr;
                int w1 = (kw + 4 + tig) * BSTRW + n0 + gr;
                bfh[ni][0] = bh[w0]; bfh[ni][1] = bh[w1];
                bfl[ni][0] = bl[w0]; bfl[ni][1] = bl[w1];
            }
            // product-major ordering: dependent MMAs on the same acc are 32 apart
#pragma unroll
            for (int mi = 0; mi < 4; mi++)
#pragma unroll
                for (int ni = 0; ni < 8; ni++)
                    mma_bf16(acc[mi][ni], afl[mi], bfh[ni]);   // lo*hi
#pragma unroll
            for (int mi = 0; mi < 4; mi++)
#pragma unroll
                for (int ni = 0; ni < 8; ni++)
                    mma_bf16(acc[mi][ni], afh[mi], bfl[ni]);   // hi*lo
#pragma unroll
            for (int mi = 0; mi < 4; mi++)
#pragma unroll
                for (int ni = 0; ni < 8; ni++)
                    mma_bf16(acc[mi][ni], afh[mi], bfh[ni]);   // hi*hi
        }
        __syncthreads();
    }
}

// ----- GEMM1: qkv = x @ Wqkv with fused RoPE(+scale)+fp16 epilogue -> g_qkvh -----
__global__ __launch_bounds__(128, 2) void gemm1_kernel(
    const unsigned* __restrict__ Agh, const unsigned* __restrict__ Agl,
    const unsigned* __restrict__ Bgh, const unsigned* __restrict__ Bgl,
    int M, int N, int K)
{
    extern __shared__ unsigned smw[];
    const int tid  = threadIdx.x;
    const int lane = tid & 31, warp = tid >> 5;
    const int wr = warp >> 1, wc = warp & 1;
    const int gr = lane >> 2, tig = lane & 3;
    const int row0 = blockIdx.y * 128, col0 = blockIdx.x * 128;

    const int bb = row0 / TT;
    const int len = g_len[bb];
    if ((row0 % TT) >= len) return;     // dead row-tile: outputs never read

    float acc[4][8][4];
    gemm_mainloop(smw, acc, Agh, Agl, Bgh, Bgl, row0, col0, K, N, tid, wr, wc, gr, tig);

    // stage fp32 tile in smem (mainloop buffers are dead now)
    float* stg = (float*)smw;
#pragma unroll
    for (int mi = 0; mi < 4; mi++) {
        int mr = wr * 64 + mi * 16;
#pragma unroll
        for (int ni = 0; ni < 8; ni++) {
            int n0 = wc * 64 + ni * 8 + 2 * tig;
            *(float2*)&stg[(mr + gr) * STGSTR + n0] =
                make_float2(acc[mi][ni][0], acc[mi][ni][1]);
            *(float2*)&stg[(mr + 8 + gr) * STGSTR + n0] =
                make_float2(acc[mi][ni][2], acc[mi][ni][3]);
        }
    }
    __syncthreads();

    const int sec = col0 / CC;             // 0=Q, 1=K, 2=V
    const int h = (col0 % CC) / DD;        // head
    const int jw = tid & 63;
    const int r2 = tid >> 6;
    const float scale = 0.08838834764831845f;

    for (int it = 0; it < 64; it++) {
        int r = r2 + it * 2;
        int t = (row0 % TT) + r;
        if (t >= len) continue;
        size_t whead = ((size_t)(bb * TT + t)) * (C3/2) + (size_t)sec * (CC/2) + (size_t)h * 64;
        float out0, out1;
        if (sec == 2) {
            float2 v = *(float2*)&stg[r * STGSTR + 2 * jw];
            out0 = v.x; out1 = v.y;
        } else if (jw < 32) {
            int cidx = 2 * jw;
            float2 x1 = *(float2*)&stg[r * STGSTR + cidx];
            float2 x2 = *(float2*)&stg[r * STGSTR + cidx + 64];
            float c0 = g_cos[t * 64 + cidx],     s0 = g_sin[t * 64 + cidx];
            float c1 = g_cos[t * 64 + cidx + 1], s1 = g_sin[t * 64 + cidx + 1];
            out0 = x1.x * c0 - x2.x * s0;
            out1 = x1.y * c1 - x2.y * s1;
            if (sec == 0) { out0 *= scale; out1 *= scale; }
        } else {
            int cidx = 2 * jw;
            int cc = cidx - 64;
            float2 x2 = *(float2*)&stg[r * STGSTR + cidx];
            float2 x1 = *(float2*)&stg[r * STGSTR + cc];
            float c0 = g_cos[t * 64 + cc],     s0 = g_sin[t * 64 + cc];
            float c1 = g_cos[t * 64 + cc + 1], s1 = g_sin[t * 64 + cc + 1];
            out0 = x2.x * c0 + x1.x * s0;
            out1 = x2.y * c1 + x1.y * s1;
            if (sec == 0) { out0 *= scale; out1 *= scale; }
        }
        g_qkvh[whead + jw] = pack_h2(out0, out1);
    }
}

// ----- GEMM2: out = attn @ Wout, fp32 epilogue; dead row-tiles -> zeros -----
__global__ __launch_bounds__(128, 2) void gemm2_kernel(
    const unsigned* __restrict__ Agh, const unsigned* __restrict__ Agl,
    const unsigned* __restrict__ Bgh, const unsigned* __restrict__ Bgl,
    float* __restrict__ C, int M, int N, int K)
{
    extern __shared__ unsigned smw[];
    const int tid  = threadIdx.x;
    const int lane = tid & 31, warp = tid >> 5;
    const int wr = warp >> 1, wc = warp & 1;
    const int gr = lane >> 2, tig = lane & 3;
    const int row0 = blockIdx.y * 128, col0 = blockIdx.x * 128;

    const int bb = row0 / TT;
    const int len = g_len[bb];
    if ((row0 % TT) >= len) {
#pragma unroll
        for (int mi = 0; mi < 4; mi++) {
            int m0 = row0 + wr * 64 + mi * 16;
#pragma unroll
            for (int ni = 0; ni < 8; ni++) {
                int n0 = col0 + wc * 64 + ni * 8 + 2 * tig;
                float* p0 = C + (size_t)(m0 + gr) * N + n0;
                float* p1 = C + (size_t)(m0 + 8 + gr) * N + n0;
                p0[0] = 0.f; p0[1] = 0.f;
                p1[0] = 0.f; p1[1] = 0.f;
            }
        }
        return;
    }

    float acc[4][8][4];
    gemm_mainloop(smw, acc, Agh, Agl, Bgh, Bgl, row0, col0, K, N, tid, wr, wc, gr, tig);

#pragma unroll
    for (int mi = 0; mi < 4; mi++) {
        int m0 = row0 + wr * 64 + mi * 16;
#pragma unroll
        for (int ni = 0; ni < 8; ni++) {
            int n0 = col0 + wc * 64 + ni * 8 + 2 * tig;
            float* p0 = C + (size_t)(m0 + gr) * N + n0;
            float* p1 = C + (size_t)(m0 + 8 + gr) * N + n0;
            p0[0] = acc[mi][ni][0]; p0[1] = acc[mi][ni][1];
            p1[0] = acc[mi][ni][2]; p1[1] = acc[mi][ni][3];
        }
    }
}

// ====== FA-2 attention, all-fp16 operands: BLK_M=128, 8 warps x (m16 x n64) ======
#define HSTR 68
#define SMW_Q 0
#define SMW_K (128 * HSTR)
#define SMW_V (SMW_K + 64 * HSTR)
#define ATT_SMEM_W (SMW_V + 64 * HSTR)
#define ATT_SMEM_BYTES (ATT_SMEM_W * 4)

__global__ __launch_bounds__(256, 1) void attn_kernel() {
    extern __shared__ unsigned smu[];
    unsigned* Qw = smu + SMW_Q;
    unsigned* Kw = smu + SMW_K;
    unsigned* Vw = smu + SMW_V;
    const unsigned vbase = smem_u32(smu + SMW_V);

    const int tid = threadIdx.x;
    const int lane = tid & 31, wid = tid >> 5;
    const int gr = lane >> 2, tig = lane & 3;
    const int m0 = wid * 16;
    const int bh = blockIdx.y;
    const int b = bh >> 4, h = bh & 15;
    const int qi = (int)gridDim.x - 1 - (int)blockIdx.x;   // heavy tiles first
    const int qbase = qi * 128;

    const int len = g_len[b];
    if (qbase >= len) return;

    const unsigned* Qg = g_qkvh + (size_t)b * TT * (C3/2) + (size_t)h * 64;
    const unsigned* Kg = Qg + (CC/2);
    const unsigned* Vg = Qg + 2 * (CC/2);

#pragma unroll
    for (int l = 0; l < 8; l++) {
        int chunk = l * 256 + tid;
        int row = chunk >> 4, c4 = (chunk & 15) << 2;
        asm volatile("cp.async.cg.shared.global [%0], [%1], 16;"
                     :: "r"(smem_u32(Qw + row * HSTR + c4)),
                        "l"(Qg + (size_t)(qbase + row) * (C3/2) + c4));
    }
    asm volatile("cp.async.commit_group;" ::: "memory");

    float mo0 = -INFINITY, mo1 = -INFINITY, lr0 = 0.f, lr1 = 0.f;
    float oacc[16][4];
#pragma unroll
    for (int ni = 0; ni < 16; ni++)
#pragma unroll
        for (int r = 0; r < 4; r++) oacc[ni][r] = 0.f;

    const int nkt = 2 * qi + 2;
    for (int kt = 0; kt < nkt; kt++) {
#pragma unroll
        for (int l = 0; l < 4; l++) {
            int chunk = l * 256 + tid;
            int row = chunk >> 4, c4 = (chunk & 15) << 2;
            size_t gofs = (size_t)(kt * 64 + row) * (C3/2) + c4;
            asm volatile("cp.async.cg.shared.global [%0], [%1], 16;"
                         :: "r"(smem_u32(Kw + row * HSTR + c4)), "l"(Kg + gofs));
            asm volatile("cp.async.cg.shared.global [%0], [%1], 16;"
                         :: "r"(smem_u32(Vw + row * HSTR + c4)), "l"(Vg + gofs));
        }
        asm volatile("cp.async.commit_group;" ::: "memory");
        asm volatile("cp.async.wait_group 0;" ::: "memory");
        __syncthreads();

        float sa[8][4];
#pragma unroll
        for (int ni = 0; ni < 8; ni++)
#pragma unroll
            for (int r = 0; r < 4; r++) sa[ni][r] = 0.f;

#pragma unroll
        for (int ks = 0; ks < 8; ks++) {
            const int k0 = ks * 8;
            unsigned a[4];
            a[0] = Qw[(m0 + gr)     * HSTR + k0 + tig];
            a[1] = Qw[(m0 + 8 + gr) * HSTR + k0 + tig];
            a[2] = Qw[(m0 + gr)     * HSTR + k0 + 4 + tig];
            a[3] = Qw[(m0 + 8 + gr) * HSTR + k0 + 4 + tig];
#pragma unroll
            for (int ni = 0; ni < 8; ni++) {
                unsigned bfr[2];
                bfr[0] = Kw[(ni * 8 + gr) * HSTR + k0 + tig];
                bfr[1] = Kw[(ni * 8 + gr) * HSTR + k0 + 4 + tig];
                mma_f16(sa[ni], a, bfr);
            }
        }

        if (kt >= 2 * qi) {
            int r0 = qbase + m0 + gr, r1 = r0 + 8;
#pragma unroll
            for (int ni = 0; ni < 8; ni++) {
                int c0 = kt * 64 + ni * 8 + 2 * tig;
                if (c0     > r0) sa[ni][0] = -INFINITY;
                if (c0 + 1 > r0) sa[ni][1] = -INFINITY;
                if (c0     > r1) sa[ni][2] = -INFINITY;
                if (c0 + 1 > r1) sa[ni][3] = -INFINITY;
            }
        }

        float mx0 = -INFINITY, mx1 = -INFINITY;
#pragma unroll
        for (int ni = 0; ni < 8; ni++) {
            mx0 = fmaxf(mx0, fmaxf(sa[ni][0], sa[ni][1]));
            mx1 = fmaxf(mx1, fmaxf(sa[ni][2], sa[ni][3]));
        }
        mx0 = fmaxf(mx0, __shfl_xor_sync(0xffffffffu, mx0, 1));
        mx0 = fmaxf(mx0, __shfl_xor_sync(0xffffffffu, mx0, 2));
        mx1 = fmaxf(mx1, __shfl_xor_sync(0xffffffffu, mx1, 1));
        mx1 = fmaxf(mx1, __shfl_xor_sync(0xffffffffu, mx1, 2));
        float mn0 = fmaxf(mo0, mx0), mn1 = fmaxf(mo1, mx1);
        float cf0 = (mo0 == -INFINITY) ? 0.f : __expf(mo0 - mn0);
        float cf1 = (mo1 == -INFINITY) ? 0.f : __expf(mo1 - mn1);

        unsigned ph[8][2];
        float s0 = 0.f, s1 = 0.f;
#pragma unroll
        for (int ni = 0; ni < 8; ni++) {
            float p0 = (sa[ni][0] == -INFINITY) ? 0.f : __expf(sa[ni][0] - mn0);
            float p1 = (sa[ni][1] == -INFINITY) ? 0.f : __expf(sa[ni][1] - mn0);
            float p2 = (sa[ni][2] == -INFINITY) ? 0.f : __expf(sa[ni][2] - mn1);
            float p3 = (sa[ni][3] == -INFINITY) ? 0.f : __expf(sa[ni][3] - mn1);
            s0 += p0 + p1; s1 += p2 + p3;
            ph[ni][0] = pack_h2(p0, p1);
            ph[ni][1] = pack_h2(p2, p3);
        }
        s0 += __shfl_xor_sync(0xffffffffu, s0, 1);
        s0 += __shfl_xor_sync(0xffffffffu, s0, 2);
        s1 += __shfl_xor_sync(0xffffffffu, s1, 1);
        s1 += __shfl_xor_sync(0xffffffffu, s1, 2);
        lr0 = lr0 * cf0 + s0; mo0 = mn0;
        lr1 = lr1 * cf1 + s1; mo1 = mn1;

#pragma unroll
        for (int ni = 0; ni < 16; ni++) {
            oacc[ni][0] *= cf0; oacc[ni][1] *= cf0;
            oacc[ni][2] *= cf1; oacc[ni][3] *= cf1;
        }

        unsigned pa[4][4];
#pragma unroll
        for (int j = 0; j < 4; j++) {
            pa[j][0] = ph[2 * j][0];
            pa[j][1] = ph[2 * j][1];
            pa[j][2] = ph[2 * j + 1][0];
            pa[j][3] = ph[2 * j + 1][1];
        }

#pragma unroll
        for (int jj = 0; jj < 2; jj++) {
            int vrow = 32 * jj + lane;
#pragma unroll
            for (int ni = 0; ni < 16; ni++) {
                unsigned d[4];
                ldsm_x4_trans(d, vbase + vrow * (HSTR * 4) + ni * 16);
                mma_f16(oacc[ni], pa[2 * jj],     d);
                mma_f16(oacc[ni], pa[2 * jj + 1], d + 2);
            }
        }
        __syncthreads();
    }

    // epilogue: normalize, zero padded rows, write bf16 hi/lo (A operand of out-GEMM)
    {
        int r0 = m0 + gr, r1 = m0 + 8 + gr;
        int t0 = qbase + r0, t1 = qbase + r1;
        float inv0 = (t0 < len) ? 1.0f / lr0 : 0.f;
        float inv1 = (t1 < len) ? 1.0f / lr1 : 0.f;
        size_t base0 = (((size_t)b * TT + t0) * CC + (size_t)h * DD) >> 1;
        size_t base1 = (((size_t)b * TT + t1) * CC + (size_t)h * DD) >> 1;
#pragma unroll
        for (int ni = 0; ni < 16; ni++) {
            int w = ni * 4 + tig;
            float o0 = oacc[ni][0] * inv0, o1 = oacc[ni][1] * inv0;
            float o2 = oacc[ni][2] * inv1, o3 = oacc[ni][3] * inv1;
            float l0, l1, l2, l3;
            g_ah[base0 + w] = pack_hi(o0, o1, l0, l1);
            g_al[base0 + w] = pack_bf(l0, l1);
            g_ah[base1 + w] = pack_hi(o2, o3, l2, l3);
            g_al[base1 + w] = pack_bf(l2, l3);
        }
    }
}

// ---------------- launch ----------------
extern "C" void kernel_launch(void* const* d_in, const int* in_sizes, int n_in,
                              void* d_out, int out_size) {
    const float* x    = (const float*)d_in[0];
    const void*  mask = d_in[1];
    const float* Wqkv = (const float*)d_in[2];
    const float* Wout = (const float*)d_in[3];
    float* out = (float*)d_out;

    unsigned *xh, *xl, *ah, *al, *wqh, *wql, *woh, *wol;
    cudaGetSymbolAddress((void**)&xh,  g_xh);
    cudaGetSymbolAddress((void**)&xl,  g_xl);
    cudaGetSymbolAddress((void**)&ah,  g_ah);
    cudaGetSymbolAddress((void**)&al,  g_al);
    cudaGetSymbolAddress((void**)&wqh, g_wqkvh);
    cudaGetSymbolAddress((void**)&wql, g_wqkvl);
    cudaGetSymbolAddress((void**)&woh, g_wouth);
    cudaGetSymbolAddress((void**)&wol, g_woutl);

    // merged prep: splits + rope tables + lengths (all independent)
    prep_kernel<<<NBLK_PREP, 256>>>(x, mask, Wqkv, Wout);

    cudaFuncSetAttribute(gemm1_kernel, cudaFuncAttributeMaxDynamicSharedMemorySize, GEMM_SMEM);
    cudaFuncSetAttribute(gemm2_kernel, cudaFuncAttributeMaxDynamicSharedMemorySize, GEMM_SMEM);

    // qkv(fp16, rotated, scaled) = RoPE(x @ Wqkv) — fused epilogue, dead tiles skipped
    gemm1_kernel<<<dim3(C3 / 128, BT / 128), 128, GEMM_SMEM>>>(
        xh, xl, wqh, wql, BT, C3, CC);

    // causal flash attention (all-fp16, warp-local softmax, dead q-tiles skipped)
    cudaFuncSetAttribute(attn_kernel, cudaFuncAttributeMaxDynamicSharedMemorySize, ATT_SMEM_BYTES);
    attn_kernel<<<dim3(TT / 128, BB * HH), 256, ATT_SMEM_BYTES>>>();

    // out = attn @ Wout  (bf16x3; dead row-tiles -> zeros)
    gemm2_kernel<<<dim3(CC / 128, BT / 128), 128, GEMM_SMEM>>>(
        ah, al, woh, wol, out, BT, CC, CC);
}